// round 6
// baseline (speedup 1.0000x reference)
#include <cuda_runtime.h>
#include <math.h>
#include <stdint.h>

#define D 768
#define K2 1536
#define BATCH 4
#define TSEQ 2048
#define NLEV 11
#define EPSV 1.1920928955078125e-07f

// ---------------- scratch (device globals) ----------------
__device__ __align__(256) float g_S[6288384 + 64];
__device__ __align__(256) float g_ctxA[6291456];
__device__ __align__(256) float g_ctxB[6291456];
__device__ __align__(256) float g_XP[6291456];
__device__ __align__(256) float g_GT[6291456];
__device__ __align__(256) float g_SPK[6291456];
__device__ __align__(256) float g_SSQ[24 * 8192];
__device__ __align__(256) float g_INV[8192];

// ---------------- helpers ----------------
__device__ __forceinline__ uint32_t smem_u32(const void* p) {
    uint32_t a;
    asm("{ .reg .u64 t; cvta.to.shared.u64 t, %1; cvt.u32.u64 %0, t; }" : "=r"(a) : "l"(p));
    return a;
}

// ================= TF32 mma.sync GEMM =================
// out[r][n] = act( concat(A0[r], A1[r]) @ W + bias )
// W is [K2][D] row-major, consumed as col-major B fragments. Raw fp32 bits are
// fed to mma.tf32 (HW truncates mantissa).
// blockIdx.x in [0, ntiles): proj -> outP + SSQ partials; [ntiles, 2*ntiles): sel -> outG
template <int BN, int WROWS>
__global__ void __launch_bounds__(256, 1)
gemm_mma(const float* __restrict__ A0, int ldA0,
         const float* __restrict__ A1, int ldA1,
         const float* __restrict__ Wp, const float* __restrict__ Ws,
         const float* __restrict__ bp, const float* __restrict__ bs,
         float* __restrict__ outP, float* __restrict__ outG,
         float* __restrict__ SSQ, int M) {
    constexpr int BM = 128, BK = 32, STAGES = 3;
    constexpr int LDA = BK + 4;
    constexpr int LDB = BN + 8;
    constexpr int A_ELE = BM * LDA;
    constexpr int B_ELE = BK * LDB;
    constexpr int WARP_M = BM / WROWS;
    constexpr int MT = WARP_M / 16;
    constexpr int NTL = 4;
    constexpr int ACHUNK = BM * 8 / 256;
    constexpr int BCHUNK = (BK * BN / 4) / 256;
    constexpr int NITER = K2 / BK;
    constexpr int WN = 8 / WROWS;          // warps along n

    extern __shared__ float sm[];
    float* sA = sm;
    float* sB = sm + STAGES * A_ELE;
    const uint32_t sA_u = smem_u32(sA);
    const uint32_t sB_u = smem_u32(sB);

    const int tid = threadIdx.x;
    const int wid = tid >> 5, lane = tid & 31;
    const int g = lane >> 2, tig = lane & 3;
    const int warpM = wid % WROWS, warpN = wid / WROWS;

    const int ntiles = 768 / BN;
    const bool isSel = ((int)blockIdx.x >= ntiles);
    const int tileIdx = isSel ? blockIdx.x - ntiles : blockIdx.x;
    const int nbase = tileIdx * BN;
    const float* __restrict__ W = isSel ? Ws : Wp;
    const float* __restrict__ bias = isSel ? bs : bp;
    float* __restrict__ out = isSel ? outG : outP;
    const int rowBase = blockIdx.y * BM;

    float c[MT][NTL][4];
    #pragma unroll
    for (int mt = 0; mt < MT; mt++)
        #pragma unroll
        for (int nt = 0; nt < NTL; nt++)
            #pragma unroll
            for (int j = 0; j < 4; j++) c[mt][nt][j] = 0.0f;

    auto issue = [&](int it) {
        const int s = it % STAGES;
        const float* src; int ld, kc;
        if (it < 24) { src = A0; ld = ldA0; kc = it * BK; }
        else         { src = A1; ld = ldA1; kc = (it - 24) * BK; }
        #pragma unroll
        for (int i = 0; i < ACHUNK; i++) {
            int idx = tid + i * 256;
            int row = idx >> 3, q = idx & 7;
            int gr = rowBase + row;
            uint32_t dst = sA_u + (uint32_t)(s * A_ELE + row * LDA + q * 4) * 4u;
            const float* gsrc = src + (size_t)gr * ld + kc + q * 4;
            int sz = (gr < M) ? 16 : 0;
            asm volatile("cp.async.cg.shared.global [%0], [%1], 16, %2;"
                         :: "r"(dst), "l"(gsrc), "r"(sz));
        }
        const int kb = it * BK;
        #pragma unroll
        for (int i = 0; i < BCHUNK; i++) {
            int idx = tid + i * 256;
            int row = idx / (BN / 4), q = idx % (BN / 4);
            uint32_t dst = sB_u + (uint32_t)(s * B_ELE + row * LDB + q * 4) * 4u;
            const float* gsrc = W + (size_t)(kb + row) * D + nbase + q * 4;
            asm volatile("cp.async.cg.shared.global [%0], [%1], 16, 16;"
                         :: "r"(dst), "l"(gsrc));
        }
        asm volatile("cp.async.commit_group;" ::: "memory");
    };

    #pragma unroll
    for (int it = 0; it < STAGES - 1; it++) issue(it);

    for (int it = 0; it < NITER; it++) {
        if (it + STAGES - 1 < NITER) issue(it + STAGES - 1);
        else asm volatile("cp.async.commit_group;" ::: "memory");
        asm volatile("cp.async.wait_group %0;" :: "n"(STAGES - 1));
        __syncthreads();

        const int s = it % STAGES;
        const float* As_ = sA + s * A_ELE;
        const float* Bs_ = sB + s * B_ELE;
        #pragma unroll
        for (int kk = 0; kk < 4; kk++) {
            uint32_t a[MT][4];
            #pragma unroll
            for (int mt = 0; mt < MT; mt++) {
                int r = warpM * WARP_M + mt * 16 + g;
                int cx = kk * 8 + tig;
                a[mt][0] = __float_as_uint(As_[r * LDA + cx]);
                a[mt][1] = __float_as_uint(As_[(r + 8) * LDA + cx]);
                a[mt][2] = __float_as_uint(As_[r * LDA + cx + 4]);
                a[mt][3] = __float_as_uint(As_[(r + 8) * LDA + cx + 4]);
            }
            uint32_t b[NTL][2];
            #pragma unroll
            for (int nt = 0; nt < NTL; nt++) {
                int n = warpN * 32 + nt * 8 + g;
                b[nt][0] = __float_as_uint(Bs_[(kk * 8 + tig) * LDB + n]);
                b[nt][1] = __float_as_uint(Bs_[(kk * 8 + tig + 4) * LDB + n]);
            }
            #pragma unroll
            for (int mt = 0; mt < MT; mt++)
                #pragma unroll
                for (int nt = 0; nt < NTL; nt++)
                    asm volatile(
                        "mma.sync.aligned.m16n8k8.row.col.f32.tf32.tf32.f32 "
                        "{%0,%1,%2,%3}, {%4,%5,%6,%7}, {%8,%9}, {%0,%1,%2,%3};"
                        : "+f"(c[mt][nt][0]), "+f"(c[mt][nt][1]),
                          "+f"(c[mt][nt][2]), "+f"(c[mt][nt][3])
                        : "r"(a[mt][0]), "r"(a[mt][1]), "r"(a[mt][2]), "r"(a[mt][3]),
                          "r"(b[nt][0]), "r"(b[nt][1]));
        }
        __syncthreads();
    }

    // ---- epilogue: bias (+sigmoid), fp32 store, proj also emits sumsq partials ----
    #pragma unroll
    for (int mt = 0; mt < MT; mt++) {
        #pragma unroll
        for (int i = 0; i < 2; i++) {
            int gr = rowBase + warpM * WARP_M + mt * 16 + g + i * 8;
            float ss = 0.0f;
            #pragma unroll
            for (int nt = 0; nt < NTL; nt++) {
                int col = nbase + warpN * 32 + nt * 8 + tig * 2;
                float v0 = c[mt][nt][i * 2 + 0] + bias[col];
                float v1 = c[mt][nt][i * 2 + 1] + bias[col + 1];
                if (isSel) {
                    v0 = 1.0f / (1.0f + expf(-v0));
                    v1 = 1.0f / (1.0f + expf(-v1));
                } else {
                    ss += v0 * v0 + v1 * v1;
                }
                if (gr < M)
                    *reinterpret_cast<float2*>(out + (size_t)gr * D + col) = make_float2(v0, v1);
            }
            if (!isSel) {
                ss += __shfl_xor_sync(0xffffffffu, ss, 1);
                ss += __shfl_xor_sync(0xffffffffu, ss, 2);
                if (tig == 0 && gr < M)
                    SSQ[(size_t)(tileIdx * WN + warpN) * M + gr] = ss;
            }
        }
    }
}

// ---------------- inv: INV[r] = rsqrt(mean(xp^2)+eps) ----------------
__global__ void inv_k(const float* __restrict__ ssq, float* __restrict__ inv, int M) {
    int r = blockIdx.x * 256 + threadIdx.x;
    if (r >= M) return;
    float s = 0.0f;
    #pragma unroll
    for (int p = 0; p < 24; p++) s += ssq[(size_t)p * M + r];
    inv[r] = rsqrtf(s * (1.0f / (float)D) + EPSV);
}

// ---------------- LIF (rmsnorm fused): chunked 64-tap recurrence ----------------
__global__ void lif_chunk(const float* __restrict__ xp, float* __restrict__ spk,
                          const float* __restrict__ inv, const float* __restrict__ nw,
                          const float* __restrict__ tau_a, const float* __restrict__ th_a,
                          int Tn, int nchunks) {
    int idx = blockIdx.x * 256 + threadIdx.x;
    int total = BATCH * D * nchunks;
    if (idx >= total) return;
    int d = idx % D;
    int rest = idx / D;
    int chunk = rest % nchunks;
    int b = rest / nchunks;
    float tau = tau_a[d], th = th_a[d], wd = nw[d];
    const float* col = xp + (size_t)b * Tn * D + d;
    const float* invb = inv + (size_t)b * Tn;
    float* so = spk + (size_t)b * Tn * D + d;
    int t0 = chunk * 256;
    int tend = t0 + 256; if (tend > Tn) tend = Tn;
    int ws = t0 - 63; if (ws < 0) ws = 0;
    float v = 0.0f;
    for (int t = ws; t < t0; t++)
        v = fmaf(tau, v, col[(size_t)t * D] * invb[t] * wd);
    for (int t = t0; t < tend; t++) {
        v = fmaf(tau, v, col[(size_t)t * D] * invb[t] * wd);
        so[(size_t)t * D] = (v >= th) ? 1.0f : 0.0f;
    }
}

// ---------------- block reduce (192 threads) ----------------
__device__ __forceinline__ float blockReduceSum192(float v) {
    __shared__ float sh[6];
    __shared__ float s_tot;
    int lane = threadIdx.x & 31;
    int wd = threadIdx.x >> 5;
    #pragma unroll
    for (int o = 16; o > 0; o >>= 1) v += __shfl_down_sync(0xffffffffu, v, o);
    if (lane == 0) sh[wd] = v;
    __syncthreads();
    if (wd == 0) {
        float t = (lane < 6) ? sh[lane] : 0.0f;
        #pragma unroll
        for (int o = 4; o > 0; o >>= 1) t += __shfl_down_sync(0xffffffffu, t, o);
        if (lane == 0) s_tot = t;
    }
    __syncthreads();
    return s_tot;
}

// ---------------- combines (192 threads, float4) ----------------
__global__ void combine_up(const float4* __restrict__ xp, const float4* __restrict__ gt,
                           const float4* __restrict__ spk, const float* __restrict__ cur,
                           float4* __restrict__ outS) {
    const int r = blockIdx.x;
    const int i = threadIdx.x;
    const size_t o = (size_t)r * 192 + i;
    float4 sp = spk[o];
    float denom = blockReduceSum192(sp.x + sp.y + sp.z + sp.w);
    denom = denom > 1.0f ? denom : 1.0f;
    float id = 1.0f / denom;
    float4 xv = xp[o], gv = gt[o];
    const float4* crow = reinterpret_cast<const float4*>(cur + (size_t)r * K2);
    float4 c0 = crow[i], c1 = crow[i + 192];
    float4 out;
    out.x = gv.x * (xv.x + sp.x * id) + (1.0f - gv.x) * 0.5f * (c0.x + c1.x);
    out.y = gv.y * (xv.y + sp.y * id) + (1.0f - gv.y) * 0.5f * (c0.y + c1.y);
    out.z = gv.z * (xv.z + sp.z * id) + (1.0f - gv.z) * 0.5f * (c0.z + c1.z);
    out.w = gv.w * (xv.w + sp.w * id) + (1.0f - gv.w) * 0.5f * (c0.w + c1.w);
    outS[o] = out;
}

__global__ void combine_down(const float4* __restrict__ xp, const float4* __restrict__ gt,
                             const float4* __restrict__ spk, const float4* __restrict__ ctx,
                             float4* __restrict__ ctxN) {
    const int r = blockIdx.x;
    const int i = threadIdx.x;
    const size_t o = (size_t)r * 192 + i;
    float4 sp = spk[o];
    float denom = blockReduceSum192(sp.x + sp.y + sp.z + sp.w);
    denom = denom > 1.0f ? denom : 1.0f;
    float id = 1.0f / denom;
    float4 xv = xp[o], gv = gt[o], cv = ctx[o];
    float4 cr;
    cr.x = gv.x * (xv.x + sp.x * id) + (1.0f - gv.x) * cv.x;
    cr.y = gv.y * (xv.y + sp.y * id) + (1.0f - gv.y) * cv.y;
    cr.z = gv.z * (xv.z + sp.z * id) + (1.0f - gv.z) * cv.z;
    cr.w = gv.w * (xv.w + sp.w * id) + (1.0f - gv.w) * cv.w;
    ctxN[(size_t)(2 * r) * 192 + i] = cv;
    ctxN[(size_t)(2 * r + 1) * 192 + i] = cr;
}

__global__ void combine_leaf(const float4* __restrict__ xp, const float4* __restrict__ gt,
                             const float4* __restrict__ spk, const float4* __restrict__ x,
                             float4* __restrict__ out) {
    const int r = blockIdx.x;
    const int i = threadIdx.x;
    const size_t o = (size_t)r * 192 + i;
    float4 sp = spk[o];
    float denom = blockReduceSum192(sp.x + sp.y + sp.z + sp.w);
    denom = denom > 1.0f ? denom : 1.0f;
    float id = 1.0f / denom;
    float4 xv = xp[o], gv = gt[o], x0 = x[o];
    float4 ov;
    ov.x = gv.x * (xv.x + sp.x * id) + (1.0f - gv.x) * x0.x;
    ov.y = gv.y * (xv.y + sp.y * id) + (1.0f - gv.y) * x0.y;
    ov.z = gv.z * (xv.z + sp.z * id) + (1.0f - gv.z) * x0.z;
    ov.w = gv.w * (xv.w + sp.w * id) + (1.0f - gv.w) * x0.w;
    out[o] = ov;
}

__global__ void zero_k(float* __restrict__ p, int n) {
    int i = blockIdx.x * 256 + threadIdx.x;
    if (i < n) p[i] = 0.0f;
}

// ---------------- launcher ----------------
extern "C" void kernel_launch(void* const* d_in, const int* in_sizes, int n_in,
                              void* d_out, int out_size) {
    const float* x     = (const float*)d_in[0];
    const float* upW   = (const float*)d_in[1];
    const float* upB   = (const float*)d_in[2];
    const float* upSW  = (const float*)d_in[3];
    const float* upSB  = (const float*)d_in[4];
    const float* upNW  = (const float*)d_in[5];
    const float* upTH  = (const float*)d_in[6];
    const float* upTAU = (const float*)d_in[7];
    const float* dnW   = (const float*)d_in[8];
    const float* dnB   = (const float*)d_in[9];
    const float* dnSW  = (const float*)d_in[10];
    const float* dnSB  = (const float*)d_in[11];
    const float* dnNW  = (const float*)d_in[12];
    const float* dnTH  = (const float*)d_in[13];
    const float* dnTAU = (const float*)d_in[14];
    const float* lfSW  = (const float*)d_in[15];
    const float* lfSB  = (const float*)d_in[16];
    const float* lfW   = (const float*)d_in[17];
    const float* lfB   = (const float*)d_in[18];
    const float* lfNW  = (const float*)d_in[19];
    const float* lfTH  = (const float*)d_in[20];
    const float* lfTAU = (const float*)d_in[21];
    float* out = (float*)d_out;

    float *S, *cA, *cB, *XP, *GT, *SPK, *SSQ, *INV;
    cudaGetSymbolAddress((void**)&S, g_S);
    cudaGetSymbolAddress((void**)&cA, g_ctxA);
    cudaGetSymbolAddress((void**)&cB, g_ctxB);
    cudaGetSymbolAddress((void**)&XP, g_XP);
    cudaGetSymbolAddress((void**)&GT, g_GT);
    cudaGetSymbolAddress((void**)&SPK, g_SPK);
    cudaGetSymbolAddress((void**)&SSQ, g_SSQ);
    cudaGetSymbolAddress((void**)&INV, g_INV);

    const int SMEM128 = (3 * 128 * 36 + 3 * 32 * 136) * 4;
    const int SMEM64  = (3 * 128 * 36 + 3 * 32 * 72) * 4;
    cudaFuncSetAttribute(gemm_mma<128, 2>, cudaFuncAttributeMaxDynamicSharedMemorySize, SMEM128);
    cudaFuncSetAttribute(gemm_mma<64, 4>,  cudaFuncAttributeMaxDynamicSharedMemorySize, SMEM64);

    auto launch_gemm = [&](const float* A0, int ldA0, const float* A1, int ldA1,
                           const float* Wpp, const float* Wss,
                           const float* bpp, const float* bss, int M) {
        if (M >= 512) {
            dim3 g(12, (M + 127) / 128);
            gemm_mma<128, 2><<<g, 256, SMEM128>>>(A0, ldA0, A1, ldA1, Wpp, Wss, bpp, bss, XP, GT, SSQ, M);
        } else {
            dim3 g(24, (M + 127) / 128);
            gemm_mma<64, 4><<<g, 256, SMEM64>>>(A0, ldA0, A1, ldA1, Wpp, Wss, bpp, bss, XP, GT, SSQ, M);
        }
        inv_k<<<(M + 255) / 256, 256>>>(SSQ, INV, M);
    };

    size_t soff[NLEV + 1];
    soff[1] = 0;
    for (int k = 1; k < NLEV; k++)
        soff[k + 1] = soff[k] + (size_t)BATCH * (TSEQ >> k) * D;

    // ---- up pass ----
    const float* cur = x;
    int Tl = TSEQ;
    for (int l = 0; l < NLEV; l++) {
        int Tn = Tl >> 1;
        int M = BATCH * Tn;
        float* Sout = S + soff[l + 1];
        launch_gemm(cur, K2, cur + D, K2,
                    upW + (size_t)l * K2 * D, upSW + (size_t)l * K2 * D,
                    upB + (size_t)l * D, upSB + (size_t)l * D, M);
        int nch = (Tn + 255) / 256;
        int tot = BATCH * D * nch;
        lif_chunk<<<(tot + 255) / 256, 256>>>(XP, SPK, INV, upNW + (size_t)l * D,
                                              upTAU + (size_t)l * D, upTH + (size_t)l * D, Tn, nch);
        combine_up<<<M, 192>>>((const float4*)XP, (const float4*)GT, (const float4*)SPK,
                               cur, (float4*)Sout);
        cur = Sout;
        Tl = Tn;
    }

    // ---- down pass ----
    zero_k<<<(BATCH * D + 255) / 256, 256>>>(cA, BATCH * D);
    float* ctx = cA;
    float* ctxN = cB;
    int n = 1;
    for (int l = NLEV; l >= 1; l--) {
        int i = l - 1;
        int M = BATCH * n;
        const float* child = (i == 0) ? x : (S + soff[i]);
        launch_gemm(ctx, D, child, 2 * D,
                    dnW + (size_t)i * K2 * D, dnSW + (size_t)i * K2 * D,
                    dnB + (size_t)i * D, dnSB + (size_t)i * D, M);
        int nch = (n + 255) / 256;
        int tot = BATCH * D * nch;
        lif_chunk<<<(tot + 255) / 256, 256>>>(XP, SPK, INV, dnNW + (size_t)i * D,
                                              dnTAU + (size_t)i * D, dnTH + (size_t)i * D, n, nch);
        combine_down<<<M, 192>>>((const float4*)XP, (const float4*)GT, (const float4*)SPK,
                                 (const float4*)ctx, (float4*)ctxN);
        float* tmp = ctx; ctx = ctxN; ctxN = tmp;
        n <<= 1;
    }

    // ---- leaf fusion ----
    {
        int M = BATCH * TSEQ;
        launch_gemm(x, D, ctx, D, lfW, lfSW, lfB, lfSB, M);
        int nch = (TSEQ + 255) / 256;
        int tot = BATCH * D * nch;
        lif_chunk<<<(tot + 255) / 256, 256>>>(XP, SPK, INV, lfNW, lfTAU, lfTH, TSEQ, nch);
        combine_leaf<<<M, 192>>>((const float4*)XP, (const float4*)GT, (const float4*)SPK,
                                 (const float4*)x, (float4*)out);
    }
}

// round 7
// speedup vs baseline: 1.5031x; 1.5031x over previous
#include <cuda_runtime.h>
#include <math.h>
#include <stdint.h>

#define D 768
#define K2 1536
#define BATCH 4
#define TSEQ 2048
#define NLEV 11
#define EPSV 1.1920928955078125e-07f

// ---------------- scratch (device globals) ----------------
__device__ __align__(256) float g_S[6288384 + 64];
__device__ __align__(256) float g_ctxA[6291456];
__device__ __align__(256) float g_ctxB[6291456];
__device__ __align__(256) float g_XP[6291456];
__device__ __align__(256) float g_GT[6291456];
__device__ __align__(256) float g_XN[6291456];
__device__ __align__(256) float g_SPK[6291456];

// ---------------- helpers ----------------
__device__ __forceinline__ uint32_t smem_u32(const void* p) {
    uint32_t a;
    asm("{ .reg .u64 t; cvta.to.shared.u64 t, %1; cvt.u32.u64 %0, t; }" : "=r"(a) : "l"(p));
    return a;
}
__device__ __forceinline__ uint32_t f2tf32(float f) {
    uint32_t r;
    asm("cvt.rna.tf32.f32 %0, %1;" : "=r"(r) : "f"(f));
    return r;
}

// ================= TF32 mma.sync GEMM (R5-proven version) =================
template <int BN, int WROWS>
__global__ void __launch_bounds__(256, 1)
gemm_mma(const float* __restrict__ A0, int ldA0,
         const float* __restrict__ A1, int ldA1,
         const float* __restrict__ Wp, const float* __restrict__ Ws,
         const float* __restrict__ bp, const float* __restrict__ bs,
         float* __restrict__ outP, float* __restrict__ outG, int M) {
    constexpr int BM = 128, BK = 32, STAGES = 3;
    constexpr int LDA = BK + 4;
    constexpr int LDB = BN + 8;
    constexpr int A_ELE = BM * LDA;
    constexpr int B_ELE = BK * LDB;
    constexpr int WARP_M = BM / WROWS;
    constexpr int MT = WARP_M / 16;
    constexpr int NTL = 4;
    constexpr int ACHUNK = BM * 8 / 256;
    constexpr int BCHUNK = (BK * BN / 4) / 256;
    constexpr int NITER = K2 / BK;

    extern __shared__ float sm[];
    float* sA = sm;
    float* sB = sm + STAGES * A_ELE;
    const uint32_t sA_u = smem_u32(sA);
    const uint32_t sB_u = smem_u32(sB);

    const int tid = threadIdx.x;
    const int wid = tid >> 5, lane = tid & 31;
    const int g = lane >> 2, tig = lane & 3;
    const int warpM = wid % WROWS, warpN = wid / WROWS;

    const int ntiles = 768 / BN;
    const bool isSel = ((int)blockIdx.x >= ntiles);
    const int nbase = (isSel ? blockIdx.x - ntiles : blockIdx.x) * BN;
    const float* __restrict__ W = isSel ? Ws : Wp;
    const float* __restrict__ bias = isSel ? bs : bp;
    float* __restrict__ out = isSel ? outG : outP;
    const int rowBase = blockIdx.y * BM;

    float c[MT][NTL][4];
    #pragma unroll
    for (int mt = 0; mt < MT; mt++)
        #pragma unroll
        for (int nt = 0; nt < NTL; nt++)
            #pragma unroll
            for (int j = 0; j < 4; j++) c[mt][nt][j] = 0.0f;

    auto issue = [&](int it) {
        const int s = it % STAGES;
        const float* src; int ld, kc;
        if (it < 24) { src = A0; ld = ldA0; kc = it * BK; }
        else         { src = A1; ld = ldA1; kc = (it - 24) * BK; }
        #pragma unroll
        for (int i = 0; i < ACHUNK; i++) {
            int idx = tid + i * 256;
            int row = idx >> 3, q = idx & 7;
            int gr = rowBase + row;
            uint32_t dst = sA_u + (uint32_t)(s * A_ELE + row * LDA + q * 4) * 4u;
            const float* gsrc = src + (size_t)gr * ld + kc + q * 4;
            int sz = (gr < M) ? 16 : 0;
            asm volatile("cp.async.cg.shared.global [%0], [%1], 16, %2;"
                         :: "r"(dst), "l"(gsrc), "r"(sz));
        }
        const int kb = it * BK;
        #pragma unroll
        for (int i = 0; i < BCHUNK; i++) {
            int idx = tid + i * 256;
            int row = idx / (BN / 4), q = idx % (BN / 4);
            uint32_t dst = sB_u + (uint32_t)(s * B_ELE + row * LDB + q * 4) * 4u;
            const float* gsrc = W + (size_t)(kb + row) * D + nbase + q * 4;
            asm volatile("cp.async.cg.shared.global [%0], [%1], 16, 16;"
                         :: "r"(dst), "l"(gsrc));
        }
        asm volatile("cp.async.commit_group;" ::: "memory");
    };

    #pragma unroll
    for (int it = 0; it < STAGES - 1; it++) issue(it);

    for (int it = 0; it < NITER; it++) {
        if (it + STAGES - 1 < NITER) issue(it + STAGES - 1);
        else asm volatile("cp.async.commit_group;" ::: "memory");
        asm volatile("cp.async.wait_group %0;" :: "n"(STAGES - 1));
        __syncthreads();

        const int s = it % STAGES;
        const float* As_ = sA + s * A_ELE;
        const float* Bs_ = sB + s * B_ELE;
        #pragma unroll
        for (int kk = 0; kk < 4; kk++) {
            uint32_t a[MT][4];
            #pragma unroll
            for (int mt = 0; mt < MT; mt++) {
                int r = warpM * WARP_M + mt * 16 + g;
                int cx = kk * 8 + tig;
                a[mt][0] = f2tf32(As_[r * LDA + cx]);
                a[mt][1] = f2tf32(As_[(r + 8) * LDA + cx]);
                a[mt][2] = f2tf32(As_[r * LDA + cx + 4]);
                a[mt][3] = f2tf32(As_[(r + 8) * LDA + cx + 4]);
            }
            uint32_t b[NTL][2];
            #pragma unroll
            for (int nt = 0; nt < NTL; nt++) {
                int n = warpN * 32 + nt * 8 + g;
                b[nt][0] = f2tf32(Bs_[(kk * 8 + tig) * LDB + n]);
                b[nt][1] = f2tf32(Bs_[(kk * 8 + tig + 4) * LDB + n]);
            }
            #pragma unroll
            for (int mt = 0; mt < MT; mt++)
                #pragma unroll
                for (int nt = 0; nt < NTL; nt++)
                    asm volatile(
                        "mma.sync.aligned.m16n8k8.row.col.f32.tf32.tf32.f32 "
                        "{%0,%1,%2,%3}, {%4,%5,%6,%7}, {%8,%9}, {%0,%1,%2,%3};"
                        : "+f"(c[mt][nt][0]), "+f"(c[mt][nt][1]),
                          "+f"(c[mt][nt][2]), "+f"(c[mt][nt][3])
                        : "r"(a[mt][0]), "r"(a[mt][1]), "r"(a[mt][2]), "r"(a[mt][3]),
                          "r"(b[nt][0]), "r"(b[nt][1]));
        }
        __syncthreads();
    }

    #pragma unroll
    for (int mt = 0; mt < MT; mt++) {
        #pragma unroll
        for (int i = 0; i < 2; i++) {
            int gr = rowBase + warpM * WARP_M + mt * 16 + g + i * 8;
            if (gr >= M) continue;
            #pragma unroll
            for (int nt = 0; nt < NTL; nt++) {
                int col = nbase + warpN * 32 + nt * 8 + tig * 2;
                float v0 = c[mt][nt][i * 2 + 0] + bias[col];
                float v1 = c[mt][nt][i * 2 + 1] + bias[col + 1];
                if (isSel) {
                    v0 = 1.0f / (1.0f + expf(-v0));
                    v1 = 1.0f / (1.0f + expf(-v1));
                }
                *reinterpret_cast<float2*>(out + (size_t)gr * D + col) = make_float2(v0, v1);
            }
        }
    }
}

// ---------------- block reduce (192 threads) ----------------
__device__ __forceinline__ float blockReduceSum192(float v) {
    __shared__ float sh[6];
    __shared__ float s_tot;
    int lane = threadIdx.x & 31;
    int wd = threadIdx.x >> 5;
    #pragma unroll
    for (int o = 16; o > 0; o >>= 1) v += __shfl_down_sync(0xffffffffu, v, o);
    if (lane == 0) sh[wd] = v;
    __syncthreads();
    if (wd == 0) {
        float t = (lane < 6) ? sh[lane] : 0.0f;
        #pragma unroll
        for (int o = 4; o > 0; o >>= 1) t += __shfl_down_sync(0xffffffffu, t, o);
        if (lane == 0) s_tot = t;
    }
    __syncthreads();
    return s_tot;
}

// ---------------- RMSNorm (float4, 192 threads) ----------------
__global__ void rmsnorm_k(const float4* __restrict__ xp, const float4* __restrict__ w,
                          float4* __restrict__ xn) {
    const int r = blockIdx.x;
    const int i = threadIdx.x;
    const size_t o = (size_t)r * 192 + i;
    float4 v = xp[o];
    float ss = v.x * v.x + v.y * v.y + v.z * v.z + v.w * v.w;
    float tot = blockReduceSum192(ss);
    float inv = rsqrtf(tot * (1.0f / (float)D) + EPSV);
    float4 wv = w[i];
    float4 r4;
    r4.x = v.x * inv * wv.x;
    r4.y = v.y * inv * wv.y;
    r4.z = v.z * inv * wv.z;
    r4.w = v.w * inv * wv.w;
    xn[o] = r4;
}

// ---------------- LIF: chunked 64-tap recurrence on XN ----------------
__global__ void lif_chunk(const float* __restrict__ xn, float* __restrict__ spk,
                          const float* __restrict__ tau_a, const float* __restrict__ th_a,
                          int Tn, int nchunks) {
    int idx = blockIdx.x * 256 + threadIdx.x;
    int total = BATCH * D * nchunks;
    if (idx >= total) return;
    int d = idx % D;
    int rest = idx / D;
    int chunk = rest % nchunks;
    int b = rest / nchunks;
    float tau = tau_a[d], th = th_a[d];
    const float* col = xn + (size_t)b * Tn * D + d;
    float* so = spk + (size_t)b * Tn * D + d;
    int t0 = chunk * 256;
    int tend = t0 + 256; if (tend > Tn) tend = Tn;
    int ws = t0 - 63; if (ws < 0) ws = 0;
    float v = 0.0f;
    for (int t = ws; t < t0; t++) v = fmaf(tau, v, col[(size_t)t * D]);
    for (int t = t0; t < tend; t++) {
        v = fmaf(tau, v, col[(size_t)t * D]);
        so[(size_t)t * D] = (v >= th) ? 1.0f : 0.0f;
    }
}

// ---------------- combines (192 threads, float4) ----------------
__global__ void combine_up(const float4* __restrict__ xp, const float4* __restrict__ gt,
                           const float4* __restrict__ spk, const float* __restrict__ cur,
                           float4* __restrict__ outS) {
    const int r = blockIdx.x;
    const int i = threadIdx.x;
    const size_t o = (size_t)r * 192 + i;
    float4 sp = spk[o];
    float denom = blockReduceSum192(sp.x + sp.y + sp.z + sp.w);
    denom = denom > 1.0f ? denom : 1.0f;
    float id = 1.0f / denom;
    float4 xv = xp[o], gv = gt[o];
    const float4* crow = reinterpret_cast<const float4*>(cur + (size_t)r * K2);
    float4 c0 = crow[i], c1 = crow[i + 192];
    float4 ov;
    ov.x = gv.x * (xv.x + sp.x * id) + (1.0f - gv.x) * 0.5f * (c0.x + c1.x);
    ov.y = gv.y * (xv.y + sp.y * id) + (1.0f - gv.y) * 0.5f * (c0.y + c1.y);
    ov.z = gv.z * (xv.z + sp.z * id) + (1.0f - gv.z) * 0.5f * (c0.z + c1.z);
    ov.w = gv.w * (xv.w + sp.w * id) + (1.0f - gv.w) * 0.5f * (c0.w + c1.w);
    outS[o] = ov;
}

__global__ void combine_down(const float4* __restrict__ xp, const float4* __restrict__ gt,
                             const float4* __restrict__ spk, const float4* __restrict__ ctx,
                             float4* __restrict__ ctxN) {
    const int r = blockIdx.x;
    const int i = threadIdx.x;
    const size_t o = (size_t)r * 192 + i;
    float4 sp = spk[o];
    float denom = blockReduceSum192(sp.x + sp.y + sp.z + sp.w);
    denom = denom > 1.0f ? denom : 1.0f;
    float id = 1.0f / denom;
    float4 xv = xp[o], gv = gt[o], cv = ctx[o];
    float4 cr;
    cr.x = gv.x * (xv.x + sp.x * id) + (1.0f - gv.x) * cv.x;
    cr.y = gv.y * (xv.y + sp.y * id) + (1.0f - gv.y) * cv.y;
    cr.z = gv.z * (xv.z + sp.z * id) + (1.0f - gv.z) * cv.z;
    cr.w = gv.w * (xv.w + sp.w * id) + (1.0f - gv.w) * cv.w;
    ctxN[(size_t)(2 * r) * 192 + i] = cv;
    ctxN[(size_t)(2 * r + 1) * 192 + i] = cr;
}

__global__ void combine_leaf(const float4* __restrict__ xp, const float4* __restrict__ gt,
                             const float4* __restrict__ spk, const float4* __restrict__ x,
                             float4* __restrict__ out) {
    const int r = blockIdx.x;
    const int i = threadIdx.x;
    const size_t o = (size_t)r * 192 + i;
    float4 sp = spk[o];
    float denom = blockReduceSum192(sp.x + sp.y + sp.z + sp.w);
    denom = denom > 1.0f ? denom : 1.0f;
    float id = 1.0f / denom;
    float4 xv = xp[o], gv = gt[o], x0 = x[o];
    float4 ov;
    ov.x = gv.x * (xv.x + sp.x * id) + (1.0f - gv.x) * x0.x;
    ov.y = gv.y * (xv.y + sp.y * id) + (1.0f - gv.y) * x0.y;
    ov.z = gv.z * (xv.z + sp.z * id) + (1.0f - gv.z) * x0.z;
    ov.w = gv.w * (xv.w + sp.w * id) + (1.0f - gv.w) * x0.w;
    out[o] = ov;
}

__global__ void zero_k(float* __restrict__ p, int n) {
    int i = blockIdx.x * 256 + threadIdx.x;
    if (i < n) p[i] = 0.0f;
}

// ---------------- launcher ----------------
extern "C" void kernel_launch(void* const* d_in, const int* in_sizes, int n_in,
                              void* d_out, int out_size) {
    const float* x     = (const float*)d_in[0];
    const float* upW   = (const float*)d_in[1];
    const float* upB   = (const float*)d_in[2];
    const float* upSW  = (const float*)d_in[3];
    const float* upSB  = (const float*)d_in[4];
    const float* upNW  = (const float*)d_in[5];
    const float* upTH  = (const float*)d_in[6];
    const float* upTAU = (const float*)d_in[7];
    const float* dnW   = (const float*)d_in[8];
    const float* dnB   = (const float*)d_in[9];
    const float* dnSW  = (const float*)d_in[10];
    const float* dnSB  = (const float*)d_in[11];
    const float* dnNW  = (const float*)d_in[12];
    const float* dnTH  = (const float*)d_in[13];
    const float* dnTAU = (const float*)d_in[14];
    const float* lfSW  = (const float*)d_in[15];
    const float* lfSB  = (const float*)d_in[16];
    const float* lfW   = (const float*)d_in[17];
    const float* lfB   = (const float*)d_in[18];
    const float* lfNW  = (const float*)d_in[19];
    const float* lfTH  = (const float*)d_in[20];
    const float* lfTAU = (const float*)d_in[21];
    float* out = (float*)d_out;

    float *S, *cA, *cB, *XP, *GT, *XN, *SPK;
    cudaGetSymbolAddress((void**)&S, g_S);
    cudaGetSymbolAddress((void**)&cA, g_ctxA);
    cudaGetSymbolAddress((void**)&cB, g_ctxB);
    cudaGetSymbolAddress((void**)&XP, g_XP);
    cudaGetSymbolAddress((void**)&GT, g_GT);
    cudaGetSymbolAddress((void**)&XN, g_XN);
    cudaGetSymbolAddress((void**)&SPK, g_SPK);

    const int SMEM128 = (3 * 128 * 36 + 3 * 32 * 136) * 4;
    const int SMEM64  = (3 * 128 * 36 + 3 * 32 * 72) * 4;
    cudaFuncSetAttribute(gemm_mma<128, 2>, cudaFuncAttributeMaxDynamicSharedMemorySize, SMEM128);
    cudaFuncSetAttribute(gemm_mma<64, 4>,  cudaFuncAttributeMaxDynamicSharedMemorySize, SMEM64);

    auto launch_gemm = [&](const float* A0, int ldA0, const float* A1, int ldA1,
                           const float* Wpp, const float* Wss,
                           const float* bpp, const float* bss, int M) {
        if (M >= 512) {
            dim3 g(12, (M + 127) / 128);
            gemm_mma<128, 2><<<g, 256, SMEM128>>>(A0, ldA0, A1, ldA1, Wpp, Wss, bpp, bss, XP, GT, M);
        } else {
            dim3 g(24, (M + 127) / 128);
            gemm_mma<64, 4><<<g, 256, SMEM64>>>(A0, ldA0, A1, ldA1, Wpp, Wss, bpp, bss, XP, GT, M);
        }
    };

    size_t soff[NLEV + 1];
    soff[1] = 0;
    for (int k = 1; k < NLEV; k++)
        soff[k + 1] = soff[k] + (size_t)BATCH * (TSEQ >> k) * D;

    // ---- up pass ----
    const float* cur = x;
    int Tl = TSEQ;
    for (int l = 0; l < NLEV; l++) {
        int Tn = Tl >> 1;
        int M = BATCH * Tn;
        float* Sout = S + soff[l + 1];
        launch_gemm(cur, K2, cur + D, K2,
                    upW + (size_t)l * K2 * D, upSW + (size_t)l * K2 * D,
                    upB + (size_t)l * D, upSB + (size_t)l * D, M);
        rmsnorm_k<<<M, 192>>>((const float4*)XP, (const float4*)(upNW + (size_t)l * D),
                              (float4*)XN);
        int nch = (Tn + 255) / 256;
        int tot = BATCH * D * nch;
        lif_chunk<<<(tot + 255) / 256, 256>>>(XN, SPK, upTAU + (size_t)l * D,
                                              upTH + (size_t)l * D, Tn, nch);
        combine_up<<<M, 192>>>((const float4*)XP, (const float4*)GT, (const float4*)SPK,
                               cur, (float4*)Sout);
        cur = Sout;
        Tl = Tn;
    }

    // ---- down pass ----
    zero_k<<<(BATCH * D + 255) / 256, 256>>>(cA, BATCH * D);
    float* ctx = cA;
    float* ctxN = cB;
    int n = 1;
    for (int l = NLEV; l >= 1; l--) {
        int i = l - 1;
        int M = BATCH * n;
        const float* child = (i == 0) ? x : (S + soff[i]);
        launch_gemm(ctx, D, child, 2 * D,
                    dnW + (size_t)i * K2 * D, dnSW + (size_t)i * K2 * D,
                    dnB + (size_t)i * D, dnSB + (size_t)i * D, M);
        rmsnorm_k<<<M, 192>>>((const float4*)XP, (const float4*)(dnNW + (size_t)i * D),
                              (float4*)XN);
        int nch = (n + 255) / 256;
        int tot = BATCH * D * nch;
        lif_chunk<<<(tot + 255) / 256, 256>>>(XN, SPK, dnTAU + (size_t)i * D,
                                              dnTH + (size_t)i * D, n, nch);
        combine_down<<<M, 192>>>((const float4*)XP, (const float4*)GT, (const float4*)SPK,
                                 (const float4*)ctx, (float4*)ctxN);
        float* tmp = ctx; ctx = ctxN; ctxN = tmp;
        n <<= 1;
    }

    // ---- leaf fusion ----
    {
        int M = BATCH * TSEQ;
        launch_gemm(x, D, ctx, D, lfW, lfSW, lfB, lfSB, M);
        rmsnorm_k<<<M, 192>>>((const float4*)XP, (const float4*)lfNW, (float4*)XN);
        int nch = (TSEQ + 255) / 256;
        int tot = BATCH * D * nch;
        lif_chunk<<<(tot + 255) / 256, 256>>>(XN, SPK, lfTAU, lfTH, TSEQ, nch);
        combine_leaf<<<M, 192>>>((const float4*)XP, (const float4*)GT, (const float4*)SPK,
                                 (const float4*)x, (float4*)out);
    }
}

// round 8
// speedup vs baseline: 2.1291x; 1.4165x over previous
#include <cuda_runtime.h>
#include <cuda_fp16.h>
#include <math.h>
#include <stdint.h>

#define D 768
#define K2 1536
#define BATCH 4
#define TSEQ 2048
#define NLEV 11
#define EPSV 1.1920928955078125e-07f
#define KD (K2 * D)

// ---------------- scratch (device globals) ----------------
__device__ __align__(256) float g_S[6288384 + 64];
__device__ __align__(256) float g_ctxA[6291456];
__device__ __align__(256) float g_ctxB[6291456];
__device__ __align__(256) float g_XP[6291456];
__device__ __align__(256) float g_GT[6291456];
__device__ __align__(256) float g_XN[6291456];
__device__ __align__(256) float g_SPK[6291456];
// fp16 GEMM operand copies
__device__ __align__(256) __half g_SH[6288384 + 64];
__device__ __align__(256) __half g_XH[6291456];
__device__ __align__(256) __half g_cAh[6291456];
__device__ __align__(256) __half g_cBh[6291456];
__device__ __align__(256) __half g_WH[46ull * K2 * D];

// ---------------- helpers ----------------
__device__ __forceinline__ uint32_t smem_u32(const void* p) {
    uint32_t a;
    asm("{ .reg .u64 t; cvta.to.shared.u64 t, %1; cvt.u32.u64 %0, t; }" : "=r"(a) : "l"(p));
    return a;
}
__device__ __forceinline__ void ldsm_x4(uint32_t& r0, uint32_t& r1, uint32_t& r2, uint32_t& r3,
                                        uint32_t addr) {
    asm volatile("ldmatrix.sync.aligned.m8n8.x4.shared.b16 {%0,%1,%2,%3}, [%4];"
                 : "=r"(r0), "=r"(r1), "=r"(r2), "=r"(r3) : "r"(addr));
}
__device__ __forceinline__ void ldsm_x4_t(uint32_t& r0, uint32_t& r1, uint32_t& r2, uint32_t& r3,
                                          uint32_t addr) {
    asm volatile("ldmatrix.sync.aligned.m8n8.x4.trans.shared.b16 {%0,%1,%2,%3}, [%4];"
                 : "=r"(r0), "=r"(r1), "=r"(r2), "=r"(r3) : "r"(addr));
}

// ---------------- conversion kernels ----------------
__global__ void convert_weights(const float* __restrict__ upW, const float* __restrict__ upSW,
                                const float* __restrict__ dnW, const float* __restrict__ dnSW,
                                const float* __restrict__ lfW, const float* __restrict__ lfSW,
                                __half2* __restrict__ WH) {
    size_t i4 = (size_t)blockIdx.x * 256 + threadIdx.x;
    size_t n4 = 46ull * KD / 4;
    if (i4 >= n4) return;
    size_t e = i4 * 4;
    int mat = (int)(e / KD);
    size_t off = e - (size_t)mat * KD;
    const float* s;
    if (mat < 11)       s = upW  + (size_t)mat * KD + off;
    else if (mat < 22)  s = upSW + (size_t)(mat - 11) * KD + off;
    else if (mat < 33)  s = dnW  + (size_t)(mat - 22) * KD + off;
    else if (mat < 44)  s = dnSW + (size_t)(mat - 33) * KD + off;
    else if (mat == 44) s = lfW + off;
    else                s = lfSW + off;
    float4 v = *reinterpret_cast<const float4*>(s);
    WH[i4 * 2 + 0] = __floats2half2_rn(v.x, v.y);
    WH[i4 * 2 + 1] = __floats2half2_rn(v.z, v.w);
}

__global__ void convert_x(const float4* __restrict__ x, __half2* __restrict__ XH, int n4) {
    int i = blockIdx.x * 256 + threadIdx.x;
    if (i >= n4) return;
    float4 v = x[i];
    XH[i * 2 + 0] = __floats2half2_rn(v.x, v.y);
    XH[i * 2 + 1] = __floats2half2_rn(v.z, v.w);
}

// ================= FP16 mma.sync GEMM =================
// out[r][n] = act( concat(A0[r], A1[r]) @ W + bias ), fp32 accumulate.
// A0/A1/W are fp16; W is [K2][D] row-major (n contiguous).
// blockIdx.x in [0, ntiles): proj -> outP ; [ntiles, 2*ntiles): sel (sigmoid) -> outG
template <int BN, int WROWS>
__global__ void __launch_bounds__(256, 1)
gemm_h(const __half* __restrict__ A0, int ldA0,
       const __half* __restrict__ A1, int ldA1,
       const __half* __restrict__ Wp, const __half* __restrict__ Ws,
       const float* __restrict__ bp, const float* __restrict__ bs,
       float* __restrict__ outP, float* __restrict__ outG, int M) {
    constexpr int BM = 128, BK = 32, STAGES = 4;
    constexpr int LDA = 40;                       // halves per A smem row (80B, conflict-free ldsm)
    constexpr int A_HALVES = BM * LDA;            // 5120
    constexpr int B_HALVES = BK * BN;
    constexpr int A_BYTES = A_HALVES * 2;
    constexpr int B_BYTES = B_HALVES * 2;
    constexpr int WARP_M = BM / WROWS;
    constexpr int MT = WARP_M / 16;
    constexpr int NTL = 4;                        // 4 x n8 per warp (32 cols)
    constexpr int BCH = (BK * BN / 8) / 256;      // B cp.async iters (16B chunks)
    constexpr int NITER = K2 / BK;                // 48

    extern __shared__ __half smh[];
    const uint32_t sA_u = smem_u32(smh);
    const uint32_t sB_u = sA_u + STAGES * A_BYTES;

    const int tid = threadIdx.x;
    const int wid = tid >> 5, lane = tid & 31;
    const int g = lane >> 2, tig = lane & 3;
    const int laneM = lane & 15, laneH = lane >> 4;
    const int warpM = wid % WROWS, warpN = wid / WROWS;

    const int ntiles = 768 / BN;
    const bool isSel = ((int)blockIdx.x >= ntiles);
    const int nbase = (isSel ? blockIdx.x - ntiles : blockIdx.x) * BN;
    const __half* __restrict__ W = isSel ? Ws : Wp;
    const float* __restrict__ bias = isSel ? bs : bp;
    float* __restrict__ out = isSel ? outG : outP;
    const int rowBase = blockIdx.y * BM;

    float c[MT][NTL][4];
    #pragma unroll
    for (int mt = 0; mt < MT; mt++)
        #pragma unroll
        for (int nt = 0; nt < NTL; nt++)
            #pragma unroll
            for (int j = 0; j < 4; j++) c[mt][nt][j] = 0.0f;

    auto issue = [&](int it) {
        const int s = it & (STAGES - 1);
        // ---- A: 128 rows x 32 halves (4 x 16B chunks per row) ----
        const __half* src; int ld, kc;
        if (it < 24) { src = A0; ld = ldA0; kc = it * BK; }
        else         { src = A1; ld = ldA1; kc = (it - 24) * BK; }
        #pragma unroll
        for (int i = 0; i < 2; i++) {
            int idx = tid + i * 256;              // 0..511
            int row = idx >> 2, ch = idx & 3;
            int gr = rowBase + row;
            uint32_t dst = sA_u + s * A_BYTES + (uint32_t)(row * LDA + ch * 8) * 2u;
            const __half* gsrc = src + (size_t)gr * ld + kc + ch * 8;
            int sz = (gr < M) ? 16 : 0;
            asm volatile("cp.async.cg.shared.global [%0], [%1], 16, %2;"
                         :: "r"(dst), "l"(gsrc), "r"(sz));
        }
        // ---- B: 32 k-rows x BN halves, XOR-swizzled 16B chunks ----
        const int kb = it * BK;
        #pragma unroll
        for (int i = 0; i < BCH; i++) {
            int idx = tid + i * 256;
            int krow = idx / (BN / 8), ch = idx % (BN / 8);
            int swc = (ch & ~7) | ((ch ^ (krow & 7)) & 7);
            uint32_t dst = sB_u + s * B_BYTES + (uint32_t)(krow * BN + swc * 8) * 2u;
            const __half* gsrc = W + (size_t)(kb + krow) * D + nbase + ch * 8;
            asm volatile("cp.async.cg.shared.global [%0], [%1], 16, 16;"
                         :: "r"(dst), "l"(gsrc));
        }
        asm volatile("cp.async.commit_group;" ::: "memory");
    };

    #pragma unroll
    for (int it = 0; it < STAGES - 1; it++) issue(it);

    for (int it = 0; it < NITER; it++) {
        if (it + STAGES - 1 < NITER) issue(it + STAGES - 1);
        else asm volatile("cp.async.commit_group;" ::: "memory");
        asm volatile("cp.async.wait_group %0;" :: "n"(STAGES - 1));
        __syncthreads();

        const int s = it & (STAGES - 1);
        const uint32_t Ab = sA_u + s * A_BYTES;
        const uint32_t Bb = sB_u + s * B_BYTES;
        #pragma unroll
        for (int ks = 0; ks < 2; ks++) {          // two k16 steps per BK=32
            uint32_t a[MT][4];
            #pragma unroll
            for (int mt = 0; mt < MT; mt++) {
                int rowA = warpM * WARP_M + mt * 16 + laneM;
                uint32_t addr = Ab + (uint32_t)(rowA * LDA + laneH * 8 + ks * 16) * 2u;
                ldsm_x4(a[mt][0], a[mt][1], a[mt][2], a[mt][3], addr);
            }
            uint32_t b[NTL][2];
            #pragma unroll
            for (int ntp = 0; ntp < 2; ntp++) {   // each trans x4 covers 2 n8 tiles
                int krow = ks * 16 + laneM;
                int ch = (warpN * 32 + ntp * 16 + laneH * 8) >> 3;
                int swc = (ch & ~7) | ((ch ^ (krow & 7)) & 7);
                uint32_t addr = Bb + (uint32_t)(krow * BN + swc * 8) * 2u;
                uint32_t r0, r1, r2, r3;
                ldsm_x4_t(r0, r1, r2, r3, addr);
                b[2 * ntp][0] = r0; b[2 * ntp][1] = r1;
                b[2 * ntp + 1][0] = r2; b[2 * ntp + 1][1] = r3;
            }
            #pragma unroll
            for (int mt = 0; mt < MT; mt++)
                #pragma unroll
                for (int nt = 0; nt < NTL; nt++)
                    asm volatile(
                        "mma.sync.aligned.m16n8k16.row.col.f32.f16.f16.f32 "
                        "{%0,%1,%2,%3}, {%4,%5,%6,%7}, {%8,%9}, {%0,%1,%2,%3};"
                        : "+f"(c[mt][nt][0]), "+f"(c[mt][nt][1]),
                          "+f"(c[mt][nt][2]), "+f"(c[mt][nt][3])
                        : "r"(a[mt][0]), "r"(a[mt][1]), "r"(a[mt][2]), "r"(a[mt][3]),
                          "r"(b[nt][0]), "r"(b[nt][1]));
        }
        __syncthreads();
    }

    // ---- epilogue: bias (+sigmoid), fp32 store ----
    #pragma unroll
    for (int mt = 0; mt < MT; mt++) {
        #pragma unroll
        for (int i = 0; i < 2; i++) {
            int gr = rowBase + warpM * WARP_M + mt * 16 + g + i * 8;
            if (gr >= M) continue;
            #pragma unroll
            for (int nt = 0; nt < NTL; nt++) {
                int col = nbase + warpN * 32 + nt * 8 + tig * 2;
                float v0 = c[mt][nt][i * 2 + 0] + bias[col];
                float v1 = c[mt][nt][i * 2 + 1] + bias[col + 1];
                if (isSel) {
                    v0 = 1.0f / (1.0f + expf(-v0));
                    v1 = 1.0f / (1.0f + expf(-v1));
                }
                *reinterpret_cast<float2*>(out + (size_t)gr * D + col) = make_float2(v0, v1);
            }
        }
    }
}

// ---------------- block reduce (192 threads) ----------------
__device__ __forceinline__ float blockReduceSum192(float v) {
    __shared__ float sh[6];
    __shared__ float s_tot;
    int lane = threadIdx.x & 31;
    int wd = threadIdx.x >> 5;
    #pragma unroll
    for (int o = 16; o > 0; o >>= 1) v += __shfl_down_sync(0xffffffffu, v, o);
    if (lane == 0) sh[wd] = v;
    __syncthreads();
    if (wd == 0) {
        float t = (lane < 6) ? sh[lane] : 0.0f;
        #pragma unroll
        for (int o = 4; o > 0; o >>= 1) t += __shfl_down_sync(0xffffffffu, t, o);
        if (lane == 0) s_tot = t;
    }
    __syncthreads();
    return s_tot;
}

// ---------------- RMSNorm (float4, 192 threads) ----------------
__global__ void rmsnorm_k(const float4* __restrict__ xp, const float4* __restrict__ w,
                          float4* __restrict__ xn) {
    const int r = blockIdx.x;
    const int i = threadIdx.x;
    const size_t o = (size_t)r * 192 + i;
    float4 v = xp[o];
    float ss = v.x * v.x + v.y * v.y + v.z * v.z + v.w * v.w;
    float tot = blockReduceSum192(ss);
    float inv = rsqrtf(tot * (1.0f / (float)D) + EPSV);
    float4 wv = w[i];
    float4 r4;
    r4.x = v.x * inv * wv.x;
    r4.y = v.y * inv * wv.y;
    r4.z = v.z * inv * wv.z;
    r4.w = v.w * inv * wv.w;
    xn[o] = r4;
}

// ---------------- LIF: chunked 64-tap recurrence on XN ----------------
__global__ void lif_chunk(const float* __restrict__ xn, float* __restrict__ spk,
                          const float* __restrict__ tau_a, const float* __restrict__ th_a,
                          int Tn, int nchunks) {
    int idx = blockIdx.x * 256 + threadIdx.x;
    int total = BATCH * D * nchunks;
    if (idx >= total) return;
    int d = idx % D;
    int rest = idx / D;
    int chunk = rest % nchunks;
    int b = rest / nchunks;
    float tau = tau_a[d], th = th_a[d];
    const float* col = xn + (size_t)b * Tn * D + d;
    float* so = spk + (size_t)b * Tn * D + d;
    int t0 = chunk * 256;
    int tend = t0 + 256; if (tend > Tn) tend = Tn;
    int ws = t0 - 63; if (ws < 0) ws = 0;
    float v = 0.0f;
    for (int t = ws; t < t0; t++) v = fmaf(tau, v, col[(size_t)t * D]);
    for (int t = t0; t < tend; t++) {
        v = fmaf(tau, v, col[(size_t)t * D]);
        so[(size_t)t * D] = (v >= th) ? 1.0f : 0.0f;
    }
}

// ---------------- combines (192 threads, float4, dual fp32+fp16 writes) ----------------
__global__ void combine_up(const float4* __restrict__ xp, const float4* __restrict__ gt,
                           const float4* __restrict__ spk, const float* __restrict__ cur,
                           float4* __restrict__ outS, __half2* __restrict__ outH) {
    const int r = blockIdx.x;
    const int i = threadIdx.x;
    const size_t o = (size_t)r * 192 + i;
    float4 sp = spk[o];
    float denom = blockReduceSum192(sp.x + sp.y + sp.z + sp.w);
    denom = denom > 1.0f ? denom : 1.0f;
    float id = 1.0f / denom;
    float4 xv = xp[o], gv = gt[o];
    const float4* crow = reinterpret_cast<const float4*>(cur + (size_t)r * K2);
    float4 c0 = crow[i], c1 = crow[i + 192];
    float4 ov;
    ov.x = gv.x * (xv.x + sp.x * id) + (1.0f - gv.x) * 0.5f * (c0.x + c1.x);
    ov.y = gv.y * (xv.y + sp.y * id) + (1.0f - gv.y) * 0.5f * (c0.y + c1.y);
    ov.z = gv.z * (xv.z + sp.z * id) + (1.0f - gv.z) * 0.5f * (c0.z + c1.z);
    ov.w = gv.w * (xv.w + sp.w * id) + (1.0f - gv.w) * 0.5f * (c0.w + c1.w);
    outS[o] = ov;
    outH[o * 2 + 0] = __floats2half2_rn(ov.x, ov.y);
    outH[o * 2 + 1] = __floats2half2_rn(ov.z, ov.w);
}

__global__ void combine_down(const float4* __restrict__ xp, const float4* __restrict__ gt,
                             const float4* __restrict__ spk, const float4* __restrict__ ctx,
                             float4* __restrict__ ctxN, __half2* __restrict__ ctxNh) {
    const int r = blockIdx.x;
    const int i = threadIdx.x;
    const size_t o = (size_t)r * 192 + i;
    float4 sp = spk[o];
    float denom = blockReduceSum192(sp.x + sp.y + sp.z + sp.w);
    denom = denom > 1.0f ? denom : 1.0f;
    float id = 1.0f / denom;
    float4 xv = xp[o], gv = gt[o], cv = ctx[o];
    float4 cr;
    cr.x = gv.x * (xv.x + sp.x * id) + (1.0f - gv.x) * cv.x;
    cr.y = gv.y * (xv.y + sp.y * id) + (1.0f - gv.y) * cv.y;
    cr.z = gv.z * (xv.z + sp.z * id) + (1.0f - gv.z) * cv.z;
    cr.w = gv.w * (xv.w + sp.w * id) + (1.0f - gv.w) * cv.w;
    size_t o0 = (size_t)(2 * r) * 192 + i;
    size_t o1 = (size_t)(2 * r + 1) * 192 + i;
    ctxN[o0] = cv;
    ctxN[o1] = cr;
    ctxNh[o0 * 2 + 0] = __floats2half2_rn(cv.x, cv.y);
    ctxNh[o0 * 2 + 1] = __floats2half2_rn(cv.z, cv.w);
    ctxNh[o1 * 2 + 0] = __floats2half2_rn(cr.x, cr.y);
    ctxNh[o1 * 2 + 1] = __floats2half2_rn(cr.z, cr.w);
}

__global__ void combine_leaf(const float4* __restrict__ xp, const float4* __restrict__ gt,
                             const float4* __restrict__ spk, const float4* __restrict__ x,
                             float4* __restrict__ out) {
    const int r = blockIdx.x;
    const int i = threadIdx.x;
    const size_t o = (size_t)r * 192 + i;
    float4 sp = spk[o];
    float denom = blockReduceSum192(sp.x + sp.y + sp.z + sp.w);
    denom = denom > 1.0f ? denom : 1.0f;
    float id = 1.0f / denom;
    float4 xv = xp[o], gv = gt[o], x0 = x[o];
    float4 ov;
    ov.x = gv.x * (xv.x + sp.x * id) + (1.0f - gv.x) * x0.x;
    ov.y = gv.y * (xv.y + sp.y * id) + (1.0f - gv.y) * x0.y;
    ov.z = gv.z * (xv.z + sp.z * id) + (1.0f - gv.z) * x0.z;
    ov.w = gv.w * (xv.w + sp.w * id) + (1.0f - gv.w) * x0.w;
    out[o] = ov;
}

__global__ void zero_ctx(float* __restrict__ p, __half* __restrict__ ph, int n) {
    int i = blockIdx.x * 256 + threadIdx.x;
    if (i < n) { p[i] = 0.0f; ph[i] = __float2half(0.0f); }
}

// ---------------- launcher ----------------
extern "C" void kernel_launch(void* const* d_in, const int* in_sizes, int n_in,
                              void* d_out, int out_size) {
    const float* x     = (const float*)d_in[0];
    const float* upW   = (const float*)d_in[1];
    const float* upB   = (const float*)d_in[2];
    const float* upSW  = (const float*)d_in[3];
    const float* upSB  = (const float*)d_in[4];
    const float* upNW  = (const float*)d_in[5];
    const float* upTH  = (const float*)d_in[6];
    const float* upTAU = (const float*)d_in[7];
    const float* dnW   = (const float*)d_in[8];
    const float* dnB   = (const float*)d_in[9];
    const float* dnSW  = (const float*)d_in[10];
    const float* dnSB  = (const float*)d_in[11];
    const float* dnNW  = (const float*)d_in[12];
    const float* dnTH  = (const float*)d_in[13];
    const float* dnTAU = (const float*)d_in[14];
    const float* lfSW  = (const float*)d_in[15];
    const float* lfSB  = (const float*)d_in[16];
    const float* lfW   = (const float*)d_in[17];
    const float* lfB   = (const float*)d_in[18];
    const float* lfNW  = (const float*)d_in[19];
    const float* lfTH  = (const float*)d_in[20];
    const float* lfTAU = (const float*)d_in[21];
    float* out = (float*)d_out;

    float *S, *cA, *cB, *XP, *GT, *XN, *SPK;
    __half *SH, *XH, *cAh, *cBh, *WH;
    cudaGetSymbolAddress((void**)&S, g_S);
    cudaGetSymbolAddress((void**)&cA, g_ctxA);
    cudaGetSymbolAddress((void**)&cB, g_ctxB);
    cudaGetSymbolAddress((void**)&XP, g_XP);
    cudaGetSymbolAddress((void**)&GT, g_GT);
    cudaGetSymbolAddress((void**)&XN, g_XN);
    cudaGetSymbolAddress((void**)&SPK, g_SPK);
    cudaGetSymbolAddress((void**)&SH, g_SH);
    cudaGetSymbolAddress((void**)&XH, g_XH);
    cudaGetSymbolAddress((void**)&cAh, g_cAh);
    cudaGetSymbolAddress((void**)&cBh, g_cBh);
    cudaGetSymbolAddress((void**)&WH, g_WH);

    // smem: 4 stages x (A 10240B + B 8192/4096B)
    const int SMEM128 = 4 * (128 * 40 * 2 + 32 * 128 * 2);   // 73728
    const int SMEM64  = 4 * (128 * 40 * 2 + 32 * 64 * 2);    // 57344
    cudaFuncSetAttribute(gemm_h<128, 2>, cudaFuncAttributeMaxDynamicSharedMemorySize, SMEM128);
    cudaFuncSetAttribute(gemm_h<64, 4>,  cudaFuncAttributeMaxDynamicSharedMemorySize, SMEM64);

    // fp16 conversions (per replay)
    {
        size_t n4 = 46ull * KD / 4;
        convert_weights<<<(unsigned)((n4 + 255) / 256), 256>>>(upW, upSW, dnW, dnSW, lfW, lfSW,
                                                               (__half2*)WH);
        int xn4 = BATCH * TSEQ * D / 4;
        convert_x<<<(xn4 + 255) / 256, 256>>>((const float4*)x, (__half2*)XH, xn4);
    }

    auto launch_gemm = [&](const __half* A0, int ldA0, const __half* A1, int ldA1,
                           const __half* Wpp, const __half* Wss,
                           const float* bpp, const float* bss, int M) {
        if (M >= 512) {
            dim3 g(12, (M + 127) / 128);
            gemm_h<128, 2><<<g, 256, SMEM128>>>(A0, ldA0, A1, ldA1, Wpp, Wss, bpp, bss, XP, GT, M);
        } else {
            dim3 g(24, (M + 127) / 128);
            gemm_h<64, 4><<<g, 256, SMEM64>>>(A0, ldA0, A1, ldA1, Wpp, Wss, bpp, bss, XP, GT, M);
        }
    };

    size_t soff[NLEV + 1];
    soff[1] = 0;
    for (int k = 1; k < NLEV; k++)
        soff[k + 1] = soff[k] + (size_t)BATCH * (TSEQ >> k) * D;

    // ---- up pass ----
    const float* cur = x;
    const __half* curH = XH;
    int Tl = TSEQ;
    for (int l = 0; l < NLEV; l++) {
        int Tn = Tl >> 1;
        int M = BATCH * Tn;
        float* Sout = S + soff[l + 1];
        __half* SoutH = SH + soff[l + 1];
        launch_gemm(curH, K2, curH + D, K2,
                    WH + (size_t)l * KD, WH + (size_t)(11 + l) * KD,
                    upB + (size_t)l * D, upSB + (size_t)l * D, M);
        rmsnorm_k<<<M, 192>>>((const float4*)XP, (const float4*)(upNW + (size_t)l * D),
                              (float4*)XN);
        int nch = (Tn + 255) / 256;
        int tot = BATCH * D * nch;
        lif_chunk<<<(tot + 255) / 256, 256>>>(XN, SPK, upTAU + (size_t)l * D,
                                              upTH + (size_t)l * D, Tn, nch);
        combine_up<<<M, 192>>>((const float4*)XP, (const float4*)GT, (const float4*)SPK,
                               cur, (float4*)Sout, (__half2*)SoutH);
        cur = Sout;
        curH = SoutH;
        Tl = Tn;
    }

    // ---- down pass ----
    zero_ctx<<<(BATCH * D + 255) / 256, 256>>>(cA, cAh, BATCH * D);
    float* ctx = cA;  __half* ctxh = cAh;
    float* ctxN = cB; __half* ctxNh = cBh;
    int n = 1;
    for (int l = NLEV; l >= 1; l--) {
        int i = l - 1;
        int M = BATCH * n;
        const __half* childH = (i == 0) ? XH : (SH + soff[i]);
        launch_gemm(ctxh, D, childH, 2 * D,
                    WH + (size_t)(22 + i) * KD, WH + (size_t)(33 + i) * KD,
                    dnB + (size_t)i * D, dnSB + (size_t)i * D, M);
        rmsnorm_k<<<M, 192>>>((const float4*)XP, (const float4*)(dnNW + (size_t)i * D),
                              (float4*)XN);
        int nch = (n + 255) / 256;
        int tot = BATCH * D * nch;
        lif_chunk<<<(tot + 255) / 256, 256>>>(XN, SPK, dnTAU + (size_t)i * D,
                                              dnTH + (size_t)i * D, n, nch);
        combine_down<<<M, 192>>>((const float4*)XP, (const float4*)GT, (const float4*)SPK,
                                 (const float4*)ctx, (float4*)ctxN, (__half2*)ctxNh);
        float* t1 = ctx; ctx = ctxN; ctxN = t1;
        __half* t2 = ctxh; ctxh = ctxNh; ctxNh = t2;
        n <<= 1;
    }

    // ---- leaf fusion ----
    {
        int M = BATCH * TSEQ;
        launch_gemm(XH, D, ctxh, D,
                    WH + 44ull * KD, WH + 45ull * KD, lfB, lfSB, M);
        rmsnorm_k<<<M, 192>>>((const float4*)XP, (const float4*)lfNW, (float4*)XN);
        int nch = (TSEQ + 255) / 256;
        int tot = BATCH * D * nch;
        lif_chunk<<<(tot + 255) / 256, 256>>>(XN, SPK, lfTAU, lfTH, TSEQ, nch);
        combine_leaf<<<M, 192>>>((const float4*)XP, (const float4*)GT, (const float4*)SPK,
                                 (const float4*)x, (float4*)out);
    }
}

// round 10
// speedup vs baseline: 2.4119x; 1.1328x over previous
#include <cuda_runtime.h>
#include <cuda_fp16.h>
#include <math.h>
#include <stdint.h>

#define D 768
#define K2 1536
#define BATCH 4
#define TSEQ 2048
#define NLEV 11
#define EPSV 1.1920928955078125e-07f
#define KD (K2 * D)

// ---------------- scratch (device globals) ----------------
__device__ __align__(256) float g_S[6288384 + 64];
__device__ __align__(256) float g_ctxA[6291456];
__device__ __align__(256) float g_ctxB[6291456];
__device__ __align__(256) float g_XP[6291456];
__device__ __align__(256) float g_GT[6291456];
__device__ __align__(256) float g_SPK[6291456];
__device__ __align__(256) float g_INV[8192];
// fp16 GEMM operand copies
__device__ __align__(256) __half g_SH[6288384 + 64];
__device__ __align__(256) __half g_XH[6291456];
__device__ __align__(256) __half g_cAh[6291456];
__device__ __align__(256) __half g_cBh[6291456];
__device__ __align__(256) __half g_WH[46ull * K2 * D];

// ---------------- helpers ----------------
__device__ __forceinline__ uint32_t smem_u32(const void* p) {
    uint32_t a;
    asm("{ .reg .u64 t; cvta.to.shared.u64 t, %1; cvt.u32.u64 %0, t; }" : "=r"(a) : "l"(p));
    return a;
}
__device__ __forceinline__ void ldsm_x4(uint32_t& r0, uint32_t& r1, uint32_t& r2, uint32_t& r3,
                                        uint32_t addr) {
    asm volatile("ldmatrix.sync.aligned.m8n8.x4.shared.b16 {%0,%1,%2,%3}, [%4];"
                 : "=r"(r0), "=r"(r1), "=r"(r2), "=r"(r3) : "r"(addr));
}
__device__ __forceinline__ void ldsm_x4_t(uint32_t& r0, uint32_t& r1, uint32_t& r2, uint32_t& r3,
                                          uint32_t addr) {
    asm volatile("ldmatrix.sync.aligned.m8n8.x4.trans.shared.b16 {%0,%1,%2,%3}, [%4];"
                 : "=r"(r0), "=r"(r1), "=r"(r2), "=r"(r3) : "r"(addr));
}

// ---------------- conversion kernels ----------------
__global__ void convert_weights(const float* __restrict__ upW, const float* __restrict__ upSW,
                                const float* __restrict__ dnW, const float* __restrict__ dnSW,
                                const float* __restrict__ lfW, const float* __restrict__ lfSW,
                                __half2* __restrict__ WH) {
    size_t i4 = (size_t)blockIdx.x * 256 + threadIdx.x;
    size_t n4 = 46ull * KD / 4;
    if (i4 >= n4) return;
    size_t e = i4 * 4;
    int mat = (int)(e / KD);
    size_t off = e - (size_t)mat * KD;
    const float* s;
    if (mat < 11)       s = upW  + (size_t)mat * KD + off;
    else if (mat < 22)  s = upSW + (size_t)(mat - 11) * KD + off;
    else if (mat < 33)  s = dnW  + (size_t)(mat - 22) * KD + off;
    else if (mat < 44)  s = dnSW + (size_t)(mat - 33) * KD + off;
    else if (mat == 44) s = lfW + off;
    else                s = lfSW + off;
    float4 v = *reinterpret_cast<const float4*>(s);
    WH[i4 * 2 + 0] = __floats2half2_rn(v.x, v.y);
    WH[i4 * 2 + 1] = __floats2half2_rn(v.z, v.w);
}

__global__ void convert_x(const float4* __restrict__ x, __half2* __restrict__ XH, int n4) {
    int i = blockIdx.x * 256 + threadIdx.x;
    if (i >= n4) return;
    float4 v = x[i];
    XH[i * 2 + 0] = __floats2half2_rn(v.x, v.y);
    XH[i * 2 + 1] = __floats2half2_rn(v.z, v.w);
}

// ================= FP16 mma.sync GEMM =================
template <int BN, int WROWS, int MAXB>
__global__ void __launch_bounds__(256, MAXB)
gemm_h(const __half* __restrict__ A0, int ldA0,
       const __half* __restrict__ A1, int ldA1,
       const __half* __restrict__ Wp, const __half* __restrict__ Ws,
       const float* __restrict__ bp, const float* __restrict__ bs,
       float* __restrict__ outP, float* __restrict__ outG, int M) {
    constexpr int BM = 128, BK = 32, STAGES = 4;
    constexpr int LDA = 40;
    constexpr int A_BYTES = BM * LDA * 2;
    constexpr int B_BYTES = BK * BN * 2;
    constexpr int WARP_M = BM / WROWS;
    constexpr int MT = WARP_M / 16;
    constexpr int NTL = 4;
    constexpr int BCH = (BK * BN / 8) / 256;
    constexpr int NITER = K2 / BK;

    extern __shared__ __half smh[];
    const uint32_t sA_u = smem_u32(smh);
    const uint32_t sB_u = sA_u + STAGES * A_BYTES;

    const int tid = threadIdx.x;
    const int wid = tid >> 5, lane = tid & 31;
    const int g = lane >> 2, tig = lane & 3;
    const int laneM = lane & 15, laneH = lane >> 4;
    const int warpM = wid % WROWS, warpN = wid / WROWS;

    const int ntiles = 768 / BN;
    const bool isSel = ((int)blockIdx.x >= ntiles);
    const int nbase = (isSel ? blockIdx.x - ntiles : blockIdx.x) * BN;
    const __half* __restrict__ W = isSel ? Ws : Wp;
    const float* __restrict__ bias = isSel ? bs : bp;
    float* __restrict__ out = isSel ? outG : outP;
    const int rowBase = blockIdx.y * BM;

    float c[MT][NTL][4];
    #pragma unroll
    for (int mt = 0; mt < MT; mt++)
        #pragma unroll
        for (int nt = 0; nt < NTL; nt++)
            #pragma unroll
            for (int j = 0; j < 4; j++) c[mt][nt][j] = 0.0f;

    auto issue = [&](int it) {
        const int s = it & (STAGES - 1);
        const __half* src; int ld, kc;
        if (it < 24) { src = A0; ld = ldA0; kc = it * BK; }
        else         { src = A1; ld = ldA1; kc = (it - 24) * BK; }
        #pragma unroll
        for (int i = 0; i < 2; i++) {
            int idx = tid + i * 256;
            int row = idx >> 2, ch = idx & 3;
            int gr = rowBase + row;
            uint32_t dst = sA_u + s * A_BYTES + (uint32_t)(row * LDA + ch * 8) * 2u;
            const __half* gsrc = src + (size_t)gr * ld + kc + ch * 8;
            int sz = (gr < M) ? 16 : 0;
            asm volatile("cp.async.cg.shared.global [%0], [%1], 16, %2;"
                         :: "r"(dst), "l"(gsrc), "r"(sz));
        }
        const int kb = it * BK;
        #pragma unroll
        for (int i = 0; i < BCH; i++) {
            int idx = tid + i * 256;
            int krow = idx / (BN / 8), ch = idx % (BN / 8);
            int swc = (ch & ~7) | ((ch ^ (krow & 7)) & 7);
            uint32_t dst = sB_u + s * B_BYTES + (uint32_t)(krow * BN + swc * 8) * 2u;
            const __half* gsrc = W + (size_t)(kb + krow) * D + nbase + ch * 8;
            asm volatile("cp.async.cg.shared.global [%0], [%1], 16, 16;"
                         :: "r"(dst), "l"(gsrc));
        }
        asm volatile("cp.async.commit_group;" ::: "memory");
    };

    #pragma unroll
    for (int it = 0; it < STAGES - 1; it++) issue(it);

    for (int it = 0; it < NITER; it++) {
        if (it + STAGES - 1 < NITER) issue(it + STAGES - 1);
        else asm volatile("cp.async.commit_group;" ::: "memory");
        asm volatile("cp.async.wait_group %0;" :: "n"(STAGES - 1));
        __syncthreads();

        const int s = it & (STAGES - 1);
        const uint32_t Ab = sA_u + s * A_BYTES;
        const uint32_t Bb = sB_u + s * B_BYTES;
        #pragma unroll
        for (int ks = 0; ks < 2; ks++) {
            uint32_t a[MT][4];
            #pragma unroll
            for (int mt = 0; mt < MT; mt++) {
                int rowA = warpM * WARP_M + mt * 16 + laneM;
                uint32_t addr = Ab + (uint32_t)(rowA * LDA + laneH * 8 + ks * 16) * 2u;
                ldsm_x4(a[mt][0], a[mt][1], a[mt][2], a[mt][3], addr);
            }
            uint32_t b[NTL][2];
            #pragma unroll
            for (int ntp = 0; ntp < 2; ntp++) {
                int krow = ks * 16 + laneM;
                int ch = (warpN * 32 + ntp * 16 + laneH * 8) >> 3;
                int swc = (ch & ~7) | ((ch ^ (krow & 7)) & 7);
                uint32_t addr = Bb + (uint32_t)(krow * BN + swc * 8) * 2u;
                uint32_t r0, r1, r2, r3;
                ldsm_x4_t(r0, r1, r2, r3, addr);
                b[2 * ntp][0] = r0; b[2 * ntp][1] = r1;
                b[2 * ntp + 1][0] = r2; b[2 * ntp + 1][1] = r3;
            }
            #pragma unroll
            for (int mt = 0; mt < MT; mt++)
                #pragma unroll
                for (int nt = 0; nt < NTL; nt++)
                    asm volatile(
                        "mma.sync.aligned.m16n8k16.row.col.f32.f16.f16.f32 "
                        "{%0,%1,%2,%3}, {%4,%5,%6,%7}, {%8,%9}, {%0,%1,%2,%3};"
                        : "+f"(c[mt][nt][0]), "+f"(c[mt][nt][1]),
                          "+f"(c[mt][nt][2]), "+f"(c[mt][nt][3])
                        : "r"(a[mt][0]), "r"(a[mt][1]), "r"(a[mt][2]), "r"(a[mt][3]),
                          "r"(b[nt][0]), "r"(b[nt][1]));
        }
        __syncthreads();
    }

    #pragma unroll
    for (int mt = 0; mt < MT; mt++) {
        #pragma unroll
        for (int i = 0; i < 2; i++) {
            int gr = rowBase + warpM * WARP_M + mt * 16 + g + i * 8;
            if (gr >= M) continue;
            #pragma unroll
            for (int nt = 0; nt < NTL; nt++) {
                int col = nbase + warpN * 32 + nt * 8 + tig * 2;
                float v0 = c[mt][nt][i * 2 + 0] + bias[col];
                float v1 = c[mt][nt][i * 2 + 1] + bias[col + 1];
                if (isSel) {
                    v0 = 1.0f / (1.0f + expf(-v0));
                    v1 = 1.0f / (1.0f + expf(-v1));
                }
                *reinterpret_cast<float2*>(out + (size_t)gr * D + col) = make_float2(v0, v1);
            }
        }
    }
}

// ---------------- block reduce (192 threads) ----------------
__device__ __forceinline__ float blockReduceSum192(float v) {
    __shared__ float sh[6];
    __shared__ float s_tot;
    int lane = threadIdx.x & 31;
    int wd = threadIdx.x >> 5;
    #pragma unroll
    for (int o = 16; o > 0; o >>= 1) v += __shfl_down_sync(0xffffffffu, v, o);
    if (lane == 0) sh[wd] = v;
    __syncthreads();
    if (wd == 0) {
        float t = (lane < 6) ? sh[lane] : 0.0f;
        #pragma unroll
        for (int o = 4; o > 0; o >>= 1) t += __shfl_down_sync(0xffffffffu, t, o);
        if (lane == 0) s_tot = t;
    }
    __syncthreads();
    return s_tot;
}

// ---------------- inv: INV[r] = rsqrt(mean(xp[r]^2)+eps) ----------------
__global__ void inv_k(const float4* __restrict__ xp, float* __restrict__ inv) {
    const int r = blockIdx.x;
    const int i = threadIdx.x;
    float4 v = xp[(size_t)r * 192 + i];
    float ss = v.x * v.x + v.y * v.y + v.z * v.z + v.w * v.w;
    float tot = blockReduceSum192(ss);
    if (i == 0) inv[r] = rsqrtf(tot * (1.0f / (float)D) + EPSV);
}

// ---------------- LIF (rmsnorm fused): chunked 64-tap recurrence on XP ----------------
__global__ void lif_chunk(const float* __restrict__ xp, float* __restrict__ spk,
                          const float* __restrict__ inv, const float* __restrict__ nw,
                          const float* __restrict__ tau_a, const float* __restrict__ th_a,
                          int Tn, int nchunks) {
    int idx = blockIdx.x * 256 + threadIdx.x;
    int total = BATCH * D * nchunks;
    if (idx >= total) return;
    int d = idx % D;
    int rest = idx / D;
    int chunk = rest % nchunks;
    int b = rest / nchunks;
    float tau = tau_a[d], th = th_a[d], wd = nw[d];
    const float* col = xp + (size_t)b * Tn * D + d;
    const float* invb = inv + (size_t)b * Tn;
    float* so = spk + (size_t)b * Tn * D + d;
    int t0 = chunk * 256;
    int tend = t0 + 256; if (tend > Tn) tend = Tn;
    int ws = t0 - 63; if (ws < 0) ws = 0;
    float v = 0.0f;
    for (int t = ws; t < t0; t++)
        v = fmaf(tau, v, col[(size_t)t * D] * invb[t] * wd);
    for (int t = t0; t < tend; t++) {
        v = fmaf(tau, v, col[(size_t)t * D] * invb[t] * wd);
        so[(size_t)t * D] = (v >= th) ? 1.0f : 0.0f;
    }
}

// ---------------- combines (192 threads, float4, dual fp32+fp16 writes) ----------------
__global__ void combine_up(const float4* __restrict__ xp, const float4* __restrict__ gt,
                           const float4* __restrict__ spk, const float* __restrict__ cur,
                           float4* __restrict__ outS, __half2* __restrict__ outH) {
    const int r = blockIdx.x;
    const int i = threadIdx.x;
    const size_t o = (size_t)r * 192 + i;
    float4 sp = spk[o];
    float denom = blockReduceSum192(sp.x + sp.y + sp.z + sp.w);
    denom = denom > 1.0f ? denom : 1.0f;
    float id = 1.0f / denom;
    float4 xv = xp[o], gv = gt[o];
    const float4* crow = reinterpret_cast<const float4*>(cur + (size_t)r * K2);
    float4 c0 = crow[i], c1 = crow[i + 192];
    float4 ov;
    ov.x = gv.x * (xv.x + sp.x * id) + (1.0f - gv.x) * 0.5f * (c0.x + c1.x);
    ov.y = gv.y * (xv.y + sp.y * id) + (1.0f - gv.y) * 0.5f * (c0.y + c1.y);
    ov.z = gv.z * (xv.z + sp.z * id) + (1.0f - gv.z) * 0.5f * (c0.z + c1.z);
    ov.w = gv.w * (xv.w + sp.w * id) + (1.0f - gv.w) * 0.5f * (c0.w + c1.w);
    outS[o] = ov;
    outH[o * 2 + 0] = __floats2half2_rn(ov.x, ov.y);
    outH[o * 2 + 1] = __floats2half2_rn(ov.z, ov.w);
}

__global__ void combine_down(const float4* __restrict__ xp, const float4* __restrict__ gt,
                             const float4* __restrict__ spk, const float4* __restrict__ ctx,
                             float4* __restrict__ ctxN, __half2* __restrict__ ctxNh) {
    const int r = blockIdx.x;
    const int i = threadIdx.x;
    const size_t o = (size_t)r * 192 + i;
    float4 sp = spk[o];
    float denom = blockReduceSum192(sp.x + sp.y + sp.z + sp.w);
    denom = denom > 1.0f ? denom : 1.0f;
    float id = 1.0f / denom;
    float4 xv = xp[o], gv = gt[o], cv = ctx[o];
    float4 cr;
    cr.x = gv.x * (xv.x + sp.x * id) + (1.0f - gv.x) * cv.x;
    cr.y = gv.y * (xv.y + sp.y * id) + (1.0f - gv.y) * cv.y;
    cr.z = gv.z * (xv.z + sp.z * id) + (1.0f - gv.z) * cv.z;
    cr.w = gv.w * (xv.w + sp.w * id) + (1.0f - gv.w) * cv.w;
    size_t o0 = (size_t)(2 * r) * 192 + i;
    size_t o1 = (size_t)(2 * r + 1) * 192 + i;
    ctxN[o0] = cv;
    ctxN[o1] = cr;
    ctxNh[o0 * 2 + 0] = __floats2half2_rn(cv.x, cv.y);
    ctxNh[o0 * 2 + 1] = __floats2half2_rn(cv.z, cv.w);
    ctxNh[o1 * 2 + 0] = __floats2half2_rn(cr.x, cr.y);
    ctxNh[o1 * 2 + 1] = __floats2half2_rn(cr.z, cr.w);
}

__global__ void combine_leaf(const float4* __restrict__ xp, const float4* __restrict__ gt,
                             const float4* __restrict__ spk, const float4* __restrict__ x,
                             float4* __restrict__ out) {
    const int r = blockIdx.x;
    const int i = threadIdx.x;
    const size_t o = (size_t)r * 192 + i;
    float4 sp = spk[o];
    float denom = blockReduceSum192(sp.x + sp.y + sp.z + sp.w);
    denom = denom > 1.0f ? denom : 1.0f;
    float id = 1.0f / denom;
    float4 xv = xp[o], gv = gt[o], x0 = x[o];
    float4 ov;
    ov.x = gv.x * (xv.x + sp.x * id) + (1.0f - gv.x) * x0.x;
    ov.y = gv.y * (xv.y + sp.y * id) + (1.0f - gv.y) * x0.y;
    ov.z = gv.z * (xv.z + sp.z * id) + (1.0f - gv.z) * x0.z;
    ov.w = gv.w * (xv.w + sp.w * id) + (1.0f - gv.w) * x0.w;
    out[o] = ov;
}

__global__ void zero_ctx(float* __restrict__ p, __half* __restrict__ ph, int n) {
    int i = blockIdx.x * 256 + threadIdx.x;
    if (i < n) { p[i] = 0.0f; ph[i] = __float2half(0.0f); }
}

// ---------------- launcher ----------------
extern "C" void kernel_launch(void* const* d_in, const int* in_sizes, int n_in,
                              void* d_out, int out_size) {
    const float* x     = (const float*)d_in[0];
    const float* upW   = (const float*)d_in[1];
    const float* upB   = (const float*)d_in[2];
    const float* upSW  = (const float*)d_in[3];
    const float* upSB  = (const float*)d_in[4];
    const float* upNW  = (const float*)d_in[5];
    const float* upTH  = (const float*)d_in[6];
    const float* upTAU = (const float*)d_in[7];
    const float* dnW   = (const float*)d_in[8];
    const float* dnB   = (const float*)d_in[9];
    const float* dnSW  = (const float*)d_in[10];
    const float* dnSB  = (const float*)d_in[11];
    const float* dnNW  = (const float*)d_in[12];
    const float* dnTH  = (const float*)d_in[13];
    const float* dnTAU = (const float*)d_in[14];
    const float* lfSW  = (const float*)d_in[15];
    const float* lfSB  = (const float*)d_in[16];
    const float* lfW   = (const float*)d_in[17];
    const float* lfB   = (const float*)d_in[18];
    const float* lfNW  = (const float*)d_in[19];
    const float* lfTH  = (const float*)d_in[20];
    const float* lfTAU = (const float*)d_in[21];
    float* out = (float*)d_out;

    float *S, *cA, *cB, *XP, *GT, *SPK, *INV;
    __half *SH, *XH, *cAh, *cBh, *WH;
    cudaGetSymbolAddress((void**)&S, g_S);
    cudaGetSymbolAddress((void**)&cA, g_ctxA);
    cudaGetSymbolAddress((void**)&cB, g_ctxB);
    cudaGetSymbolAddress((void**)&XP, g_XP);
    cudaGetSymbolAddress((void**)&GT, g_GT);
    cudaGetSymbolAddress((void**)&SPK, g_SPK);
    cudaGetSymbolAddress((void**)&INV, g_INV);
    cudaGetSymbolAddress((void**)&SH, g_SH);
    cudaGetSymbolAddress((void**)&XH, g_XH);
    cudaGetSymbolAddress((void**)&cAh, g_cAh);
    cudaGetSymbolAddress((void**)&cBh, g_cBh);
    cudaGetSymbolAddress((void**)&WH, g_WH);

    const int SMEM128 = 4 * (128 * 40 * 2 + 32 * 128 * 2);   // 73728
    const int SMEM64  = 4 * (128 * 40 * 2 + 32 * 64 * 2);    // 57344
    cudaFuncSetAttribute(gemm_h<128, 2, 2>, cudaFuncAttributeMaxDynamicSharedMemorySize, SMEM128);
    cudaFuncSetAttribute(gemm_h<64, 4, 1>,  cudaFuncAttributeMaxDynamicSharedMemorySize, SMEM64);

    {
        size_t n4 = 46ull * KD / 4;
        convert_weights<<<(unsigned)((n4 + 255) / 256), 256>>>(upW, upSW, dnW, dnSW, lfW, lfSW,
                                                               (__half2*)WH);
        int xn4 = BATCH * TSEQ * D / 4;
        convert_x<<<(xn4 + 255) / 256, 256>>>((const float4*)x, (__half2*)XH, xn4);
    }

    auto launch_gemm = [&](const __half* A0, int ldA0, const __half* A1, int ldA1,
                           const __half* Wpp, const __half* Wss,
                           const float* bpp, const float* bss, int M) {
        if (M >= 512) {
            dim3 g(12, (M + 127) / 128);
            gemm_h<128, 2, 2><<<g, 256, SMEM128>>>(A0, ldA0, A1, ldA1, Wpp, Wss, bpp, bss, XP, GT, M);
        } else {
            dim3 g(24, (M + 127) / 128);
            gemm_h<64, 4, 1><<<g, 256, SMEM64>>>(A0, ldA0, A1, ldA1, Wpp, Wss, bpp, bss, XP, GT, M);
        }
        inv_k<<<M, 192>>>((const float4*)XP, INV);
    };

    size_t soff[NLEV + 1];
    soff[1] = 0;
    for (int k = 1; k < NLEV; k++)
        soff[k + 1] = soff[k] + (size_t)BATCH * (TSEQ >> k) * D;

    // ---- up pass ----
    const float* cur = x;
    const __half* curH = XH;
    int Tl = TSEQ;
    for (int l = 0; l < NLEV; l++) {
        int Tn = Tl >> 1;
        int M = BATCH * Tn;
        float* Sout = S + soff[l + 1];
        __half* SoutH = SH + soff[l + 1];
        launch_gemm(curH, K2, curH + D, K2,
                    WH + (size_t)l * KD, WH + (size_t)(11 + l) * KD,
                    upB + (size_t)l * D, upSB + (size_t)l * D, M);
        int nch = (Tn + 255) / 256;
        int tot = BATCH * D * nch;
        lif_chunk<<<(tot + 255) / 256, 256>>>(XP, SPK, INV, upNW + (size_t)l * D,
                                              upTAU + (size_t)l * D, upTH + (size_t)l * D, Tn, nch);
        combine_up<<<M, 192>>>((const float4*)XP, (const float4*)GT, (const float4*)SPK,
                               cur, (float4*)Sout, (__half2*)SoutH);
        cur = Sout;
        curH = SoutH;
        Tl = Tn;
    }

    // ---- down pass ----
    zero_ctx<<<(BATCH * D + 255) / 256, 256>>>(cA, cAh, BATCH * D);
    float* ctx = cA;  __half* ctxh = cAh;
    float* ctxN = cB; __half* ctxNh = cBh;
    int n = 1;
    for (int l = NLEV; l >= 1; l--) {
        int i = l - 1;
        int M = BATCH * n;
        const __half* childH = (i == 0) ? XH : (SH + soff[i]);
        launch_gemm(ctxh, D, childH, 2 * D,
                    WH + (size_t)(22 + i) * KD, WH + (size_t)(33 + i) * KD,
                    dnB + (size_t)i * D, dnSB + (size_t)i * D, M);
        int nch = (n + 255) / 256;
        int tot = BATCH * D * nch;
        lif_chunk<<<(tot + 255) / 256, 256>>>(XP, SPK, INV, dnNW + (size_t)i * D,
                                              dnTAU + (size_t)i * D, dnTH + (size_t)i * D, n, nch);
        combine_down<<<M, 192>>>((const float4*)XP, (const float4*)GT, (const float4*)SPK,
                                 (const float4*)ctx, (float4*)ctxN, (__half2*)ctxNh);
        float* t1 = ctx; ctx = ctxN; ctxN = t1;
        __half* t2 = ctxh; ctxh = ctxNh; ctxNh = t2;
        n <<= 1;
    }

    // ---- leaf fusion ----
    {
        int M = BATCH * TSEQ;
        launch_gemm(XH, D, ctxh, D,
                    WH + 44ull * KD, WH + 45ull * KD, lfB, lfSB, M);
        int nch = (TSEQ + 255) / 256;
        int tot = BATCH * D * nch;
        lif_chunk<<<(tot + 255) / 256, 256>>>(XP, SPK, INV, lfNW, lfTAU, lfTH, TSEQ, nch);
        combine_leaf<<<M, 192>>>((const float4*)XP, (const float4*)GT, (const float4*)SPK,
                                 (const float4*)x, (float4*)out);
    }
}

// round 12
// speedup vs baseline: 2.8010x; 1.1613x over previous
#include <cuda_runtime.h>
#include <cuda_fp16.h>
#include <math.h>
#include <stdint.h>

#define D 768
#define K2 1536
#define BATCH 4
#define TSEQ 2048
#define NLEV 11
#define EPSV 1.1920928955078125e-07f
#define KD (K2 * D)

// ---------------- scratch (device globals) ----------------
__device__ __align__(256) float g_S[6288384 + 64];
__device__ __align__(256) float g_ctxA[6291456];
__device__ __align__(256) float g_ctxB[6291456];
__device__ __align__(256) float g_XP[6291456];
__device__ __align__(256) float g_GT[6291456];
__device__ __align__(256) float g_SPK[6291456];
__device__ __align__(256) float g_INV[8192];
__device__ __align__(256) float g_SSQ[24 * 8192];
// fp16 GEMM operand copies
__device__ __align__(256) __half g_SH[6288384 + 64];
__device__ __align__(256) __half g_XH[6291456];
__device__ __align__(256) __half g_cAh[6291456];
__device__ __align__(256) __half g_cBh[6291456];
__device__ __align__(256) __half g_WH[46ull * K2 * D];

// ---------------- helpers ----------------
__device__ __forceinline__ uint32_t smem_u32(const void* p) {
    uint32_t a;
    asm("{ .reg .u64 t; cvta.to.shared.u64 t, %1; cvt.u32.u64 %0, t; }" : "=r"(a) : "l"(p));
    return a;
}
__device__ __forceinline__ void ldsm_x4(uint32_t& r0, uint32_t& r1, uint32_t& r2, uint32_t& r3,
                                        uint32_t addr) {
    asm volatile("ldmatrix.sync.aligned.m8n8.x4.shared.b16 {%0,%1,%2,%3}, [%4];"
                 : "=r"(r0), "=r"(r1), "=r"(r2), "=r"(r3) : "r"(addr));
}
__device__ __forceinline__ void ldsm_x4_t(uint32_t& r0, uint32_t& r1, uint32_t& r2, uint32_t& r3,
                                          uint32_t addr) {
    asm volatile("ldmatrix.sync.aligned.m8n8.x4.trans.shared.b16 {%0,%1,%2,%3}, [%4];"
                 : "=r"(r0), "=r"(r1), "=r"(r2), "=r"(r3) : "r"(addr));
}

// ---------------- conversion / init kernels ----------------
__global__ void convert_weights(const float* __restrict__ upW, const float* __restrict__ upSW,
                                const float* __restrict__ dnW, const float* __restrict__ dnSW,
                                const float* __restrict__ lfW, const float* __restrict__ lfSW,
                                __half2* __restrict__ WH) {
    size_t i4 = (size_t)blockIdx.x * 256 + threadIdx.x;
    size_t n4 = 46ull * KD / 4;
    if (i4 >= n4) return;
    size_t e = i4 * 4;
    int mat = (int)(e / KD);
    size_t off = e - (size_t)mat * KD;
    const float* s;
    if (mat < 11)       s = upW  + (size_t)mat * KD + off;
    else if (mat < 22)  s = upSW + (size_t)(mat - 11) * KD + off;
    else if (mat < 33)  s = dnW  + (size_t)(mat - 22) * KD + off;
    else if (mat < 44)  s = dnSW + (size_t)(mat - 33) * KD + off;
    else if (mat == 44) s = lfW + off;
    else                s = lfSW + off;
    float4 v = *reinterpret_cast<const float4*>(s);
    WH[i4 * 2 + 0] = __floats2half2_rn(v.x, v.y);
    WH[i4 * 2 + 1] = __floats2half2_rn(v.z, v.w);
}

__global__ void convert_x(const float4* __restrict__ x, __half2* __restrict__ XH, int n4) {
    int i = blockIdx.x * 256 + threadIdx.x;
    if (i >= n4) return;
    float4 v = x[i];
    XH[i * 2 + 0] = __floats2half2_rn(v.x, v.y);
    XH[i * 2 + 1] = __floats2half2_rn(v.z, v.w);
}

__global__ void zero_ssq(float* __restrict__ ssq) {
    int i = blockIdx.x * 256 + threadIdx.x;
    if (i < 24 * 8192) ssq[i] = 0.0f;
}

// ================= FP16 mma.sync GEMM (BM=128, BK=32) =================
template <int BN, int WROWS, int MAXB>
__global__ void __launch_bounds__(256, MAXB)
gemm_h(const __half* __restrict__ A0, int ldA0,
       const __half* __restrict__ A1, int ldA1,
       const __half* __restrict__ Wp, const __half* __restrict__ Ws,
       const float* __restrict__ bp, const float* __restrict__ bs,
       float* __restrict__ outP, float* __restrict__ outG,
       float* __restrict__ SSQrow, int M) {
    constexpr int BM = 128, BK = 32, STAGES = 4;
    constexpr int LDA = 40;
    constexpr int A_BYTES = BM * LDA * 2;
    constexpr int B_BYTES = BK * BN * 2;
    constexpr int WARP_M = BM / WROWS;
    constexpr int MT = WARP_M / 16;
    constexpr int NTL = 4;
    constexpr int BCH = (BK * BN / 8) / 256;
    constexpr int NITER = K2 / BK;

    extern __shared__ __half smh[];
    const uint32_t sA_u = smem_u32(smh);
    const uint32_t sB_u = sA_u + STAGES * A_BYTES;

    const int tid = threadIdx.x;
    const int wid = tid >> 5, lane = tid & 31;
    const int g = lane >> 2, tig = lane & 3;
    const int laneM = lane & 15, laneH = lane >> 4;
    const int warpM = wid % WROWS, warpN = wid / WROWS;

    const int ntiles = 768 / BN;
    const bool isSel = ((int)blockIdx.x >= ntiles);
    const int nbase = (isSel ? blockIdx.x - ntiles : blockIdx.x) * BN;
    const __half* __restrict__ W = isSel ? Ws : Wp;
    const float* __restrict__ bias = isSel ? bs : bp;
    float* __restrict__ out = isSel ? outG : outP;
    const int rowBase = blockIdx.y * BM;

    float c[MT][NTL][4];
    #pragma unroll
    for (int mt = 0; mt < MT; mt++)
        #pragma unroll
        for (int nt = 0; nt < NTL; nt++)
            #pragma unroll
            for (int j = 0; j < 4; j++) c[mt][nt][j] = 0.0f;

    auto issue = [&](int it) {
        const int s = it & (STAGES - 1);
        const __half* src; int ld, kc;
        if (it < 24) { src = A0; ld = ldA0; kc = it * BK; }
        else         { src = A1; ld = ldA1; kc = (it - 24) * BK; }
        #pragma unroll
        for (int i = 0; i < 2; i++) {
            int idx = tid + i * 256;
            int row = idx >> 2, ch = idx & 3;
            int gr = rowBase + row;
            uint32_t dst = sA_u + s * A_BYTES + (uint32_t)(row * LDA + ch * 8) * 2u;
            const __half* gsrc = src + (size_t)gr * ld + kc + ch * 8;
            int sz = (gr < M) ? 16 : 0;
            asm volatile("cp.async.cg.shared.global [%0], [%1], 16, %2;"
                         :: "r"(dst), "l"(gsrc), "r"(sz));
        }
        const int kb = it * BK;
        #pragma unroll
        for (int i = 0; i < BCH; i++) {
            int idx = tid + i * 256;
            int krow = idx / (BN / 8), ch = idx % (BN / 8);
            int swc = (ch & ~7) | ((ch ^ (krow & 7)) & 7);
            uint32_t dst = sB_u + s * B_BYTES + (uint32_t)(krow * BN + swc * 8) * 2u;
            const __half* gsrc = W + (size_t)(kb + krow) * D + nbase + ch * 8;
            asm volatile("cp.async.cg.shared.global [%0], [%1], 16, 16;"
                         :: "r"(dst), "l"(gsrc));
        }
        asm volatile("cp.async.commit_group;" ::: "memory");
    };

    #pragma unroll
    for (int it = 0; it < STAGES - 1; it++) issue(it);

    for (int it = 0; it < NITER; it++) {
        if (it + STAGES - 1 < NITER) issue(it + STAGES - 1);
        else asm volatile("cp.async.commit_group;" ::: "memory");
        asm volatile("cp.async.wait_group %0;" :: "n"(STAGES - 1));
        __syncthreads();

        const int s = it & (STAGES - 1);
        const uint32_t Ab = sA_u + s * A_BYTES;
        const uint32_t Bb = sB_u + s * B_BYTES;
        #pragma unroll
        for (int ks = 0; ks < 2; ks++) {
            uint32_t a[MT][4];
            #pragma unroll
            for (int mt = 0; mt < MT; mt++) {
                int rowA = warpM * WARP_M + mt * 16 + laneM;
                uint32_t addr = Ab + (uint32_t)(rowA * LDA + laneH * 8 + ks * 16) * 2u;
                ldsm_x4(a[mt][0], a[mt][1], a[mt][2], a[mt][3], addr);
            }
            uint32_t b[NTL][2];
            #pragma unroll
            for (int ntp = 0; ntp < 2; ntp++) {
                int krow = ks * 16 + laneM;
                int ch = (warpN * 32 + ntp * 16 + laneH * 8) >> 3;
                int swc = (ch & ~7) | ((ch ^ (krow & 7)) & 7);
                uint32_t addr = Bb + (uint32_t)(krow * BN + swc * 8) * 2u;
                uint32_t r0, r1, r2, r3;
                ldsm_x4_t(r0, r1, r2, r3, addr);
                b[2 * ntp][0] = r0; b[2 * ntp][1] = r1;
                b[2 * ntp + 1][0] = r2; b[2 * ntp + 1][1] = r3;
            }
            #pragma unroll
            for (int mt = 0; mt < MT; mt++)
                #pragma unroll
                for (int nt = 0; nt < NTL; nt++)
                    asm volatile(
                        "mma.sync.aligned.m16n8k16.row.col.f32.f16.f16.f32 "
                        "{%0,%1,%2,%3}, {%4,%5,%6,%7}, {%8,%9}, {%0,%1,%2,%3};"
                        : "+f"(c[mt][nt][0]), "+f"(c[mt][nt][1]),
                          "+f"(c[mt][nt][2]), "+f"(c[mt][nt][3])
                        : "r"(a[mt][0]), "r"(a[mt][1]), "r"(a[mt][2]), "r"(a[mt][3]),
                          "r"(b[nt][0]), "r"(b[nt][1]));
        }
        __syncthreads();
    }

    // epilogue: bias (+sigmoid) store; proj also accumulates row sum-of-squares
    #pragma unroll
    for (int mt = 0; mt < MT; mt++) {
        #pragma unroll
        for (int i = 0; i < 2; i++) {
            int gr = rowBase + warpM * WARP_M + mt * 16 + g + i * 8;
            float ss = 0.0f;
            #pragma unroll
            for (int nt = 0; nt < NTL; nt++) {
                int col = nbase + warpN * 32 + nt * 8 + tig * 2;
                float v0 = c[mt][nt][i * 2 + 0] + bias[col];
                float v1 = c[mt][nt][i * 2 + 1] + bias[col + 1];
                if (isSel) {
                    v0 = 1.0f / (1.0f + expf(-v0));
                    v1 = 1.0f / (1.0f + expf(-v1));
                } else {
                    ss += v0 * v0 + v1 * v1;
                }
                if (gr < M)
                    *reinterpret_cast<float2*>(out + (size_t)gr * D + col) = make_float2(v0, v1);
            }
            if (!isSel) {
                ss += __shfl_xor_sync(0xffffffffu, ss, 1);
                ss += __shfl_xor_sync(0xffffffffu, ss, 2);
                if (tig == 0 && gr < M) atomicAdd(SSQrow + gr, ss);
            }
        }
    }
}

// ================= FP16 small-M GEMM (BM=32, BK=128, BN=64) =================
__global__ void __launch_bounds__(256, 2)
gemm_s(const __half* __restrict__ A0, int ldA0,
       const __half* __restrict__ A1, int ldA1,
       const __half* __restrict__ Wp, const __half* __restrict__ Ws,
       const float* __restrict__ bp, const float* __restrict__ bs,
       float* __restrict__ outP, float* __restrict__ outG,
       float* __restrict__ SSQrow, int M) {
    constexpr int BM = 32, BK = 128, BN = 64, STAGES = 3;
    constexpr int LDA = BK + 8;                   // 136 halves (272B row, conflict-free ldsm)
    constexpr int A_BYTES = BM * LDA * 2;         // 8704
    constexpr int B_BYTES = BK * BN * 2;          // 16384
    constexpr int NITER = K2 / BK;                // 12
    constexpr int NTL = 2;

    extern __shared__ __half smh[];
    const uint32_t sA_u = smem_u32(smh);
    const uint32_t sB_u = sA_u + STAGES * A_BYTES;

    const int tid = threadIdx.x;
    const int wid = tid >> 5, lane = tid & 31;
    const int g = lane >> 2, tig = lane & 3;
    const int laneM = lane & 15, laneH = lane >> 4;
    const int warpM = wid & 1, warpN = wid >> 1;  // 2 x 4

    const int ntiles = 768 / BN;                  // 12
    const bool isSel = ((int)blockIdx.x >= ntiles);
    const int nbase = (isSel ? blockIdx.x - ntiles : blockIdx.x) * BN;
    const __half* __restrict__ W = isSel ? Ws : Wp;
    const float* __restrict__ bias = isSel ? bs : bp;
    float* __restrict__ out = isSel ? outG : outP;
    const int rowBase = blockIdx.y * BM;

    float c[NTL][4];
    #pragma unroll
    for (int nt = 0; nt < NTL; nt++)
        #pragma unroll
        for (int j = 0; j < 4; j++) c[nt][j] = 0.0f;

    auto issue = [&](int it) {
        const int s = it % STAGES;
        const __half* src; int ld, kc;
        if (it < 6) { src = A0; ld = ldA0; kc = it * BK; }
        else        { src = A1; ld = ldA1; kc = (it - 6) * BK; }
        // A: 32 rows x 128 halves = 512 x 16B chunks
        #pragma unroll
        for (int i = 0; i < 2; i++) {
            int idx = tid + i * 256;
            int row = idx >> 4, ch = idx & 15;
            int gr = rowBase + row;
            uint32_t dst = sA_u + s * A_BYTES + (uint32_t)(row * LDA + ch * 8) * 2u;
            const __half* gsrc = src + (size_t)gr * ld + kc + ch * 8;
            int sz = (gr < M) ? 16 : 0;
            asm volatile("cp.async.cg.shared.global [%0], [%1], 16, %2;"
                         :: "r"(dst), "l"(gsrc), "r"(sz));
        }
        // B: 128 k-rows x 64 halves = 1024 x 16B chunks, XOR swizzle
        const int kb = it * BK;
        #pragma unroll
        for (int i = 0; i < 4; i++) {
            int idx = tid + i * 256;
            int krow = idx >> 3, ch = idx & 7;
            int swc = (ch ^ krow) & 7;
            uint32_t dst = sB_u + s * B_BYTES + (uint32_t)(krow * BN + swc * 8) * 2u;
            const __half* gsrc = W + (size_t)(kb + krow) * D + nbase + ch * 8;
            asm volatile("cp.async.cg.shared.global [%0], [%1], 16, 16;"
                         :: "r"(dst), "l"(gsrc));
        }
        asm volatile("cp.async.commit_group;" ::: "memory");
    };

    issue(0); issue(1);

    for (int it = 0; it < NITER; it++) {
        if (it + STAGES - 1 < NITER) issue(it + STAGES - 1);
        else asm volatile("cp.async.commit_group;" ::: "memory");
        asm volatile("cp.async.wait_group %0;" :: "n"(STAGES - 1));
        __syncthreads();

        const int s = it % STAGES;
        const uint32_t Ab = sA_u + s * A_BYTES;
        const uint32_t Bb = sB_u + s * B_BYTES;
        #pragma unroll
        for (int ks = 0; ks < 8; ks++) {
            uint32_t a[4];
            {
                int rowA = warpM * 16 + laneM;
                uint32_t addr = Ab + (uint32_t)(rowA * LDA + laneH * 8 + ks * 16) * 2u;
                ldsm_x4(a[0], a[1], a[2], a[3], addr);
            }
            uint32_t b[NTL][2];
            {
                int krow = ks * 16 + laneM;
                int ch = warpN * 2 + laneH;
                int swc = (ch ^ krow) & 7;
                uint32_t addr = Bb + (uint32_t)(krow * BN + swc * 8) * 2u;
                uint32_t r0, r1, r2, r3;
                ldsm_x4_t(r0, r1, r2, r3, addr);
                b[0][0] = r0; b[0][1] = r1;
                b[1][0] = r2; b[1][1] = r3;
            }
            #pragma unroll
            for (int nt = 0; nt < NTL; nt++)
                asm volatile(
                    "mma.sync.aligned.m16n8k16.row.col.f32.f16.f16.f32 "
                    "{%0,%1,%2,%3}, {%4,%5,%6,%7}, {%8,%9}, {%0,%1,%2,%3};"
                    : "+f"(c[nt][0]), "+f"(c[nt][1]), "+f"(c[nt][2]), "+f"(c[nt][3])
                    : "r"(a[0]), "r"(a[1]), "r"(a[2]), "r"(a[3]),
                      "r"(b[nt][0]), "r"(b[nt][1]));
        }
        __syncthreads();
    }

    #pragma unroll
    for (int i = 0; i < 2; i++) {
        int gr = rowBase + warpM * 16 + g + i * 8;
        float ss = 0.0f;
        #pragma unroll
        for (int nt = 0; nt < NTL; nt++) {
            int col = nbase + warpN * 16 + nt * 8 + tig * 2;
            float v0 = c[nt][i * 2 + 0] + bias[col];
            float v1 = c[nt][i * 2 + 1] + bias[col + 1];
            if (isSel) {
                v0 = 1.0f / (1.0f + expf(-v0));
                v1 = 1.0f / (1.0f + expf(-v1));
            } else {
                ss += v0 * v0 + v1 * v1;
            }
            if (gr < M)
                *reinterpret_cast<float2*>(out + (size_t)gr * D + col) = make_float2(v0, v1);
        }
        if (!isSel) {
            ss += __shfl_xor_sync(0xffffffffu, ss, 1);
            ss += __shfl_xor_sync(0xffffffffu, ss, 2);
            if (tig == 0 && gr < M) atomicAdd(SSQrow + gr, ss);
        }
    }
}

// ---------------- block reduce (192 threads) ----------------
__device__ __forceinline__ float blockReduceSum192(float v) {
    __shared__ float sh[6];
    __shared__ float s_tot;
    int lane = threadIdx.x & 31;
    int wd = threadIdx.x >> 5;
    #pragma unroll
    for (int o = 16; o > 0; o >>= 1) v += __shfl_down_sync(0xffffffffu, v, o);
    if (lane == 0) sh[wd] = v;
    __syncthreads();
    if (wd == 0) {
        float t = (lane < 6) ? sh[lane] : 0.0f;
        #pragma unroll
        for (int o = 4; o > 0; o >>= 1) t += __shfl_down_sync(0xffffffffu, t, o);
        if (lane == 0) s_tot = t;
    }
    __syncthreads();
    return s_tot;
}

// ---------------- inv from fused SSQ ----------------
__global__ void inv_k(const float* __restrict__ ssq, float* __restrict__ inv, int M) {
    int r = blockIdx.x * 256 + threadIdx.x;
    if (r < M) inv[r] = rsqrtf(ssq[r] * (1.0f / (float)D) + EPSV);
}

// ---------------- LIF (rmsnorm fused): chunked 64-tap recurrence on XP ----------------
__global__ void lif_chunk(const float* __restrict__ xp, float* __restrict__ spk,
                          const float* __restrict__ inv, const float* __restrict__ nw,
                          const float* __restrict__ tau_a, const float* __restrict__ th_a,
                          int Tn, int nchunks) {
    int idx = blockIdx.x * 256 + threadIdx.x;
    int total = BATCH * D * nchunks;
    if (idx >= total) return;
    int d = idx % D;
    int rest = idx / D;
    int chunk = rest % nchunks;
    int b = rest / nchunks;
    float tau = tau_a[d], th = th_a[d], wd = nw[d];
    const float* col = xp + (size_t)b * Tn * D + d;
    const float* invb = inv + (size_t)b * Tn;
    float* so = spk + (size_t)b * Tn * D + d;
    int t0 = chunk * 256;
    int tend = t0 + 256; if (tend > Tn) tend = Tn;
    int ws = t0 - 63; if (ws < 0) ws = 0;
    float v = 0.0f;
    for (int t = ws; t < t0; t++)
        v = fmaf(tau, v, col[(size_t)t * D] * invb[t] * wd);
    for (int t = t0; t < tend; t++) {
        v = fmaf(tau, v, col[(size_t)t * D] * invb[t] * wd);
        so[(size_t)t * D] = (v >= th) ? 1.0f : 0.0f;
    }
}

// ---------------- combines (192 threads, float4, dual fp32+fp16 writes) ----------------
__global__ void combine_up(const float4* __restrict__ xp, const float4* __restrict__ gt,
                           const float4* __restrict__ spk, const float* __restrict__ cur,
                           float4* __restrict__ outS, __half2* __restrict__ outH) {
    const int r = blockIdx.x;
    const int i = threadIdx.x;
    const size_t o = (size_t)r * 192 + i;
    float4 sp = spk[o];
    float denom = blockReduceSum192(sp.x + sp.y + sp.z + sp.w);
    denom = denom > 1.0f ? denom : 1.0f;
    float id = 1.0f / denom;
    float4 xv = xp[o], gv = gt[o];
    const float4* crow = reinterpret_cast<const float4*>(cur + (size_t)r * K2);
    float4 c0 = crow[i], c1 = crow[i + 192];
    float4 ov;
    ov.x = gv.x * (xv.x + sp.x * id) + (1.0f - gv.x) * 0.5f * (c0.x + c1.x);
    ov.y = gv.y * (xv.y + sp.y * id) + (1.0f - gv.y) * 0.5f * (c0.y + c1.y);
    ov.z = gv.z * (xv.z + sp.z * id) + (1.0f - gv.z) * 0.5f * (c0.z + c1.z);
    ov.w = gv.w * (xv.w + sp.w * id) + (1.0f - gv.w) * 0.5f * (c0.w + c1.w);
    outS[o] = ov;
    outH[o * 2 + 0] = __floats2half2_rn(ov.x, ov.y);
    outH[o * 2 + 1] = __floats2half2_rn(ov.z, ov.w);
}

__global__ void combine_down(const float4* __restrict__ xp, const float4* __restrict__ gt,
                             const float4* __restrict__ spk, const float4* __restrict__ ctx,
                             float4* __restrict__ ctxN, __half2* __restrict__ ctxNh) {
    const int r = blockIdx.x;
    const int i = threadIdx.x;
    const size_t o = (size_t)r * 192 + i;
    float4 sp = spk[o];
    float denom = blockReduceSum192(sp.x + sp.y + sp.z + sp.w);
    denom = denom > 1.0f ? denom : 1.0f;
    float id = 1.0f / denom;
    float4 xv = xp[o], gv = gt[o], cv = ctx[o];
    float4 cr;
    cr.x = gv.x * (xv.x + sp.x * id) + (1.0f - gv.x) * cv.x;
    cr.y = gv.y * (xv.y + sp.y * id) + (1.0f - gv.y) * cv.y;
    cr.z = gv.z * (xv.z + sp.z * id) + (1.0f - gv.z) * cv.z;
    cr.w = gv.w * (xv.w + sp.w * id) + (1.0f - gv.w) * cv.w;
    size_t o0 = (size_t)(2 * r) * 192 + i;
    size_t o1 = (size_t)(2 * r + 1) * 192 + i;
    ctxN[o0] = cv;
    ctxN[o1] = cr;
    ctxNh[o0 * 2 + 0] = __floats2half2_rn(cv.x, cv.y);
    ctxNh[o0 * 2 + 1] = __floats2half2_rn(cv.z, cv.w);
    ctxNh[o1 * 2 + 0] = __floats2half2_rn(cr.x, cr.y);
    ctxNh[o1 * 2 + 1] = __floats2half2_rn(cr.z, cr.w);
}

__global__ void combine_leaf(const float4* __restrict__ xp, const float4* __restrict__ gt,
                             const float4* __restrict__ spk, const float4* __restrict__ x,
                             float4* __restrict__ out) {
    const int r = blockIdx.x;
    const int i = threadIdx.x;
    const size_t o = (size_t)r * 192 + i;
    float4 sp = spk[o];
    float denom = blockReduceSum192(sp.x + sp.y + sp.z + sp.w);
    denom = denom > 1.0f ? denom : 1.0f;
    float id = 1.0f / denom;
    float4 xv = xp[o], gv = gt[o], x0 = x[o];
    float4 ov;
    ov.x = gv.x * (xv.x + sp.x * id) + (1.0f - gv.x) * x0.x;
    ov.y = gv.y * (xv.y + sp.y * id) + (1.0f - gv.y) * x0.y;
    ov.z = gv.z * (xv.z + sp.z * id) + (1.0f - gv.z) * x0.z;
    ov.w = gv.w * (xv.w + sp.w * id) + (1.0f - gv.w) * x0.w;
    out[o] = ov;
}

__global__ void zero_ctx(float* __restrict__ p, __half* __restrict__ ph, int n) {
    int i = blockIdx.x * 256 + threadIdx.x;
    if (i < n) { p[i] = 0.0f; ph[i] = __float2half(0.0f); }
}

// ---------------- launcher ----------------
extern "C" void kernel_launch(void* const* d_in, const int* in_sizes, int n_in,
                              void* d_out, int out_size) {
    const float* x     = (const float*)d_in[0];
    const float* upW   = (const float*)d_in[1];
    const float* upB   = (const float*)d_in[2];
    const float* upSW  = (const float*)d_in[3];
    const float* upSB  = (const float*)d_in[4];
    const float* upNW  = (const float*)d_in[5];
    const float* upTH  = (const float*)d_in[6];
    const float* upTAU = (const float*)d_in[7];
    const float* dnW   = (const float*)d_in[8];
    const float* dnB   = (const float*)d_in[9];
    const float* dnSW  = (const float*)d_in[10];
    const float* dnSB  = (const float*)d_in[11];
    const float* dnNW  = (const float*)d_in[12];
    const float* dnTH  = (const float*)d_in[13];
    const float* dnTAU = (const float*)d_in[14];
    const float* lfSW  = (const float*)d_in[15];
    const float* lfSB  = (const float*)d_in[16];
    const float* lfW   = (const float*)d_in[17];
    const float* lfB   = (const float*)d_in[18];
    const float* lfNW  = (const float*)d_in[19];
    const float* lfTH  = (const float*)d_in[20];
    const float* lfTAU = (const float*)d_in[21];
    float* out = (float*)d_out;

    float *S, *cA, *cB, *XP, *GT, *SPK, *INV, *SSQ;
    __half *SH, *XH, *cAh, *cBh, *WH;
    cudaGetSymbolAddress((void**)&S, g_S);
    cudaGetSymbolAddress((void**)&cA, g_ctxA);
    cudaGetSymbolAddress((void**)&cB, g_ctxB);
    cudaGetSymbolAddress((void**)&XP, g_XP);
    cudaGetSymbolAddress((void**)&GT, g_GT);
    cudaGetSymbolAddress((void**)&SPK, g_SPK);
    cudaGetSymbolAddress((void**)&INV, g_INV);
    cudaGetSymbolAddress((void**)&SSQ, g_SSQ);
    cudaGetSymbolAddress((void**)&SH, g_SH);
    cudaGetSymbolAddress((void**)&XH, g_XH);
    cudaGetSymbolAddress((void**)&cAh, g_cAh);
    cudaGetSymbolAddress((void**)&cBh, g_cBh);
    cudaGetSymbolAddress((void**)&WH, g_WH);

    const int SMEM128 = 4 * (128 * 40 * 2 + 32 * 128 * 2);   // 73728
    const int SMEMS   = 3 * (32 * 136 * 2 + 128 * 64 * 2);   // 75264
    cudaFuncSetAttribute(gemm_h<128, 2, 2>, cudaFuncAttributeMaxDynamicSharedMemorySize, SMEM128);
    cudaFuncSetAttribute(gemm_s, cudaFuncAttributeMaxDynamicSharedMemorySize, SMEMS);

    {
        size_t n4 = 46ull * KD / 4;
        convert_weights<<<(unsigned)((n4 + 255) / 256), 256>>>(upW, upSW, dnW, dnSW, lfW, lfSW,
                                                               (__half2*)WH);
        int xn4 = BATCH * TSEQ * D / 4;
        convert_x<<<(xn4 + 255) / 256, 256>>>((const float4*)x, (__half2*)XH, xn4);
        zero_ssq<<<768, 256>>>(SSQ);
    }

    int stage = 0;
    auto launch_gemm = [&](const __half* A0, int ldA0, const __half* A1, int ldA1,
                           const __half* Wpp, const __half* Wss,
                           const float* bpp, const float* bss, int M) {
        float* SSQrow = SSQ + (size_t)stage * 8192;
        stage++;
        if (M >= 1024) {
            dim3 g(12, (M + 127) / 128);
            gemm_h<128, 2, 2><<<g, 256, SMEM128>>>(A0, ldA0, A1, ldA1, Wpp, Wss, bpp, bss,
                                                   XP, GT, SSQrow, M);
        } else {
            dim3 g(24, (M + 31) / 32);
            gemm_s<<<g, 256, SMEMS>>>(A0, ldA0, A1, ldA1, Wpp, Wss, bpp, bss,
                                      XP, GT, SSQrow, M);
        }
        inv_k<<<(M + 255) / 256, 256>>>(SSQrow, INV, M);
    };

    size_t soff[NLEV + 1];
    soff[1] = 0;
    for (int k = 1; k < NLEV; k++)
        soff[k + 1] = soff[k] + (size_t)BATCH * (TSEQ >> k) * D;

    // ---- up pass ----
    const float* cur = x;
    const __half* curH = XH;
    int Tl = TSEQ;
    for (int l = 0; l < NLEV; l++) {
        int Tn = Tl >> 1;
        int M = BATCH * Tn;
        float* Sout = S + soff[l + 1];
        __half* SoutH = SH + soff[l + 1];
        launch_gemm(curH, K2, curH + D, K2,
                    WH + (size_t)l * KD, WH + (size_t)(11 + l) * KD,
                    upB + (size_t)l * D, upSB + (size_t)l * D, M);
        int nch = (Tn + 255) / 256;
        int tot = BATCH * D * nch;
        lif_chunk<<<(tot + 255) / 256, 256>>>(XP, SPK, INV, upNW + (size_t)l * D,
                                              upTAU + (size_t)l * D, upTH + (size_t)l * D, Tn, nch);
        combine_up<<<M, 192>>>((const float4*)XP, (const float4*)GT, (const float4*)SPK,
                               cur, (float4*)Sout, (__half2*)SoutH);
        cur = Sout;
        curH = SoutH;
        Tl = Tn;
    }

    // ---- down pass ----
    zero_ctx<<<(BATCH * D + 255) / 256, 256>>>(cA, cAh, BATCH * D);
    float* ctx = cA;  __half* ctxh = cAh;
    float* ctxN = cB; __half* ctxNh = cBh;
    int n = 1;
    for (int l = NLEV; l >= 1; l--) {
        int i = l - 1;
        int M = BATCH * n;
        const __half* childH = (i == 0) ? XH : (SH + soff[i]);
        launch_gemm(ctxh, D, childH, 2 * D,
                    WH + (size_t)(22 + i) * KD, WH + (size_t)(33 + i) * KD,
                    dnB + (size_t)i * D, dnSB + (size_t)i * D, M);
        int nch = (n + 255) / 256;
        int tot = BATCH * D * nch;
        lif_chunk<<<(tot + 255) / 256, 256>>>(XP, SPK, INV, dnNW + (size_t)i * D,
                                              dnTAU + (size_t)i * D, dnTH + (size_t)i * D, n, nch);
        combine_down<<<M, 192>>>((const float4*)XP, (const float4*)GT, (const float4*)SPK,
                                 (const float4*)ctx, (float4*)ctxN, (__half2*)ctxNh);
        float* t1 = ctx; ctx = ctxN; ctxN = t1;
        __half* t2 = ctxh; ctxh = ctxNh; ctxNh = t2;
        n <<= 1;
    }

    // ---- leaf fusion ----
    {
        int M = BATCH * TSEQ;
        launch_gemm(XH, D, ctxh, D,
                    WH + 44ull * KD, WH + 45ull * KD, lfB, lfSB, M);
        int nch = (TSEQ + 255) / 256;
        int tot = BATCH * D * nch;
        lif_chunk<<<(tot + 255) / 256, 256>>>(XP, SPK, INV, lfNW, lfTAU, lfTH, TSEQ, nch);
        combine_leaf<<<M, 192>>>((const float4*)XP, (const float4*)GT, (const float4*)SPK,
                                 (const float4*)x, (float4*)out);
    }
}

// round 14
// speedup vs baseline: 2.8499x; 1.0174x over previous
#include <cuda_runtime.h>
#include <cuda_fp16.h>
#include <math.h>
#include <stdint.h>

#define D 768
#define K2 1536
#define BATCH 4
#define TSEQ 2048
#define NLEV 11
#define EPSV 1.1920928955078125e-07f
#define KD (K2 * D)

// ---------------- scratch (device globals) ----------------
__device__ __align__(256) float g_S[6288384 + 64];
__device__ __align__(256) float g_ctxA[6291456];
__device__ __align__(256) float g_ctxB[6291456];
__device__ __align__(256) float g_XP[6291456];
__device__ __align__(256) float g_GT[6291456];
__device__ __align__(256) float g_SPK[6291456];
__device__ __align__(256) float g_SSQ[24 * 8192];
// fp16 GEMM operand copies
__device__ __align__(256) __half g_SH[6288384 + 64];
__device__ __align__(256) __half g_XH[6291456];
__device__ __align__(256) __half g_cAh[6291456];
__device__ __align__(256) __half g_cBh[6291456];
__device__ __align__(256) __half g_WH[46ull * K2 * D];

// ---------------- helpers ----------------
__device__ __forceinline__ uint32_t smem_u32(const void* p) {
    uint32_t a;
    asm("{ .reg .u64 t; cvta.to.shared.u64 t, %1; cvt.u32.u64 %0, t; }" : "=r"(a) : "l"(p));
    return a;
}
__device__ __forceinline__ void ldsm_x4(uint32_t& r0, uint32_t& r1, uint32_t& r2, uint32_t& r3,
                                        uint32_t addr) {
    asm volatile("ldmatrix.sync.aligned.m8n8.x4.shared.b16 {%0,%1,%2,%3}, [%4];"
                 : "=r"(r0), "=r"(r1), "=r"(r2), "=r"(r3) : "r"(addr));
}
__device__ __forceinline__ void ldsm_x4_t(uint32_t& r0, uint32_t& r1, uint32_t& r2, uint32_t& r3,
                                          uint32_t addr) {
    asm volatile("ldmatrix.sync.aligned.m8n8.x4.trans.shared.b16 {%0,%1,%2,%3}, [%4];"
                 : "=r"(r0), "=r"(r1), "=r"(r2), "=r"(r3) : "r"(addr));
}

// ---------------- conversion / init kernels ----------------
__global__ void convert_weights(const float* __restrict__ upW, const float* __restrict__ upSW,
                                const float* __restrict__ dnW, const float* __restrict__ dnSW,
                                const float* __restrict__ lfW, const float* __restrict__ lfSW,
                                __half2* __restrict__ WH) {
    size_t i4 = (size_t)blockIdx.x * 256 + threadIdx.x;
    size_t n4 = 46ull * KD / 4;
    if (i4 >= n4) return;
    size_t e = i4 * 4;
    int mat = (int)(e / KD);
    size_t off = e - (size_t)mat * KD;
    const float* s;
    if (mat < 11)       s = upW  + (size_t)mat * KD + off;
    else if (mat < 22)  s = upSW + (size_t)(mat - 11) * KD + off;
    else if (mat < 33)  s = dnW  + (size_t)(mat - 22) * KD + off;
    else if (mat < 44)  s = dnSW + (size_t)(mat - 33) * KD + off;
    else if (mat == 44) s = lfW + off;
    else                s = lfSW + off;
    float4 v = *reinterpret_cast<const float4*>(s);
    WH[i4 * 2 + 0] = __floats2half2_rn(v.x, v.y);
    WH[i4 * 2 + 1] = __floats2half2_rn(v.z, v.w);
}

__global__ void convert_x(const float4* __restrict__ x, __half2* __restrict__ XH, int n4) {
    int i = blockIdx.x * 256 + threadIdx.x;
    if (i >= n4) return;
    float4 v = x[i];
    XH[i * 2 + 0] = __floats2half2_rn(v.x, v.y);
    XH[i * 2 + 1] = __floats2half2_rn(v.z, v.w);
}

__global__ void zero_ssq(float* __restrict__ ssq) {
    int i = blockIdx.x * 256 + threadIdx.x;
    if (i < 24 * 8192) ssq[i] = 0.0f;
}

// ================= FP16 mma.sync GEMM (BM=128, BK=32) =================
template <int BN, int WROWS, int MAXB>
__global__ void __launch_bounds__(256, MAXB)
gemm_h(const __half* __restrict__ A0, int ldA0,
       const __half* __restrict__ A1, int ldA1,
       const __half* __restrict__ Wp, const __half* __restrict__ Ws,
       const float* __restrict__ bp, const float* __restrict__ bs,
       float* __restrict__ outP, float* __restrict__ outG,
       float* __restrict__ SSQrow, int M) {
    constexpr int BM = 128, BK = 32, STAGES = 4;
    constexpr int LDA = 40;
    constexpr int A_BYTES = BM * LDA * 2;
    constexpr int B_BYTES = BK * BN * 2;
    constexpr int WARP_M = BM / WROWS;
    constexpr int MT = WARP_M / 16;
    constexpr int NTL = 4;
    constexpr int BCH = (BK * BN / 8) / 256;
    constexpr int NITER = K2 / BK;

    extern __shared__ __half smh[];
    const uint32_t sA_u = smem_u32(smh);
    const uint32_t sB_u = sA_u + STAGES * A_BYTES;

    const int tid = threadIdx.x;
    const int wid = tid >> 5, lane = tid & 31;
    const int g = lane >> 2, tig = lane & 3;
    const int laneM = lane & 15, laneH = lane >> 4;
    const int warpM = wid % WROWS, warpN = wid / WROWS;

    const int ntiles = 768 / BN;
    const bool isSel = ((int)blockIdx.x >= ntiles);
    const int nbase = (isSel ? blockIdx.x - ntiles : blockIdx.x) * BN;
    const __half* __restrict__ W = isSel ? Ws : Wp;
    const float* __restrict__ bias = isSel ? bs : bp;
    float* __restrict__ out = isSel ? outG : outP;
    const int rowBase = blockIdx.y * BM;

    float c[MT][NTL][4];
    #pragma unroll
    for (int mt = 0; mt < MT; mt++)
        #pragma unroll
        for (int nt = 0; nt < NTL; nt++)
            #pragma unroll
            for (int j = 0; j < 4; j++) c[mt][nt][j] = 0.0f;

    auto issue = [&](int it) {
        const int s = it & (STAGES - 1);
        const __half* src; int ld, kc;
        if (it < 24) { src = A0; ld = ldA0; kc = it * BK; }
        else         { src = A1; ld = ldA1; kc = (it - 24) * BK; }
        #pragma unroll
        for (int i = 0; i < 2; i++) {
            int idx = tid + i * 256;
            int row = idx >> 2, ch = idx & 3;
            int gr = rowBase + row;
            uint32_t dst = sA_u + s * A_BYTES + (uint32_t)(row * LDA + ch * 8) * 2u;
            const __half* gsrc = src + (size_t)gr * ld + kc + ch * 8;
            int sz = (gr < M) ? 16 : 0;
            asm volatile("cp.async.cg.shared.global [%0], [%1], 16, %2;"
                         :: "r"(dst), "l"(gsrc), "r"(sz));
        }
        const int kb = it * BK;
        #pragma unroll
        for (int i = 0; i < BCH; i++) {
            int idx = tid + i * 256;
            int krow = idx / (BN / 8), ch = idx % (BN / 8);
            int swc = (ch & ~7) | ((ch ^ (krow & 7)) & 7);
            uint32_t dst = sB_u + s * B_BYTES + (uint32_t)(krow * BN + swc * 8) * 2u;
            const __half* gsrc = W + (size_t)(kb + krow) * D + nbase + ch * 8;
            asm volatile("cp.async.cg.shared.global [%0], [%1], 16, 16;"
                         :: "r"(dst), "l"(gsrc));
        }
        asm volatile("cp.async.commit_group;" ::: "memory");
    };

    #pragma unroll
    for (int it = 0; it < STAGES - 1; it++) issue(it);

    for (int it = 0; it < NITER; it++) {
        if (it + STAGES - 1 < NITER) issue(it + STAGES - 1);
        else asm volatile("cp.async.commit_group;" ::: "memory");
        asm volatile("cp.async.wait_group %0;" :: "n"(STAGES - 1));
        __syncthreads();

        const int s = it & (STAGES - 1);
        const uint32_t Ab = sA_u + s * A_BYTES;
        const uint32_t Bb = sB_u + s * B_BYTES;
        #pragma unroll
        for (int ks = 0; ks < 2; ks++) {
            uint32_t a[MT][4];
            #pragma unroll
            for (int mt = 0; mt < MT; mt++) {
                int rowA = warpM * WARP_M + mt * 16 + laneM;
                uint32_t addr = Ab + (uint32_t)(rowA * LDA + laneH * 8 + ks * 16) * 2u;
                ldsm_x4(a[mt][0], a[mt][1], a[mt][2], a[mt][3], addr);
            }
            uint32_t b[NTL][2];
            #pragma unroll
            for (int ntp = 0; ntp < 2; ntp++) {
                int krow = ks * 16 + laneM;
                int ch = (warpN * 32 + ntp * 16 + laneH * 8) >> 3;
                int swc = (ch & ~7) | ((ch ^ (krow & 7)) & 7);
                uint32_t addr = Bb + (uint32_t)(krow * BN + swc * 8) * 2u;
                uint32_t r0, r1, r2, r3;
                ldsm_x4_t(r0, r1, r2, r3, addr);
                b[2 * ntp][0] = r0; b[2 * ntp][1] = r1;
                b[2 * ntp + 1][0] = r2; b[2 * ntp + 1][1] = r3;
            }
            #pragma unroll
            for (int mt = 0; mt < MT; mt++)
                #pragma unroll
                for (int nt = 0; nt < NTL; nt++)
                    asm volatile(
                        "mma.sync.aligned.m16n8k16.row.col.f32.f16.f16.f32 "
                        "{%0,%1,%2,%3}, {%4,%5,%6,%7}, {%8,%9}, {%0,%1,%2,%3};"
                        : "+f"(c[mt][nt][0]), "+f"(c[mt][nt][1]),
                          "+f"(c[mt][nt][2]), "+f"(c[mt][nt][3])
                        : "r"(a[mt][0]), "r"(a[mt][1]), "r"(a[mt][2]), "r"(a[mt][3]),
                          "r"(b[nt][0]), "r"(b[nt][1]));
        }
        __syncthreads();
    }

    // epilogue: bias (+sigmoid) store; proj also accumulates row sum-of-squares
    #pragma unroll
    for (int mt = 0; mt < MT; mt++) {
        #pragma unroll
        for (int i = 0; i < 2; i++) {
            int gr = rowBase + warpM * WARP_M + mt * 16 + g + i * 8;
            float ss = 0.0f;
            #pragma unroll
            for (int nt = 0; nt < NTL; nt++) {
                int col = nbase + warpN * 32 + nt * 8 + tig * 2;
                float v0 = c[mt][nt][i * 2 + 0] + bias[col];
                float v1 = c[mt][nt][i * 2 + 1] + bias[col + 1];
                if (isSel) {
                    v0 = 1.0f / (1.0f + expf(-v0));
                    v1 = 1.0f / (1.0f + expf(-v1));
                } else {
                    ss += v0 * v0 + v1 * v1;
                }
                if (gr < M)
                    *reinterpret_cast<float2*>(out + (size_t)gr * D + col) = make_float2(v0, v1);
            }
            if (!isSel) {
                ss += __shfl_xor_sync(0xffffffffu, ss, 1);
                ss += __shfl_xor_sync(0xffffffffu, ss, 2);
                if (tig == 0 && gr < M) atomicAdd(SSQrow + gr, ss);
            }
        }
    }
}

// ================= FP16 small-M GEMM (BM=32, BK=128, BN=64, 4 stages) =================
__global__ void __launch_bounds__(256, 2)
gemm_s(const __half* __restrict__ A0, int ldA0,
       const __half* __restrict__ A1, int ldA1,
       const __half* __restrict__ Wp, const __half* __restrict__ Ws,
       const float* __restrict__ bp, const float* __restrict__ bs,
       float* __restrict__ outP, float* __restrict__ outG,
       float* __restrict__ SSQrow, int M) {
    constexpr int BM = 32, BK = 128, BN = 64, STAGES = 4;
    constexpr int LDA = BK + 8;                   // 136 halves
    constexpr int A_BYTES = BM * LDA * 2;         // 8704
    constexpr int B_BYTES = BK * BN * 2;          // 16384
    constexpr int NITER = K2 / BK;                // 12
    constexpr int NTL = 2;

    extern __shared__ __half smh[];
    const uint32_t sA_u = smem_u32(smh);
    const uint32_t sB_u = sA_u + STAGES * A_BYTES;

    const int tid = threadIdx.x;
    const int wid = tid >> 5, lane = tid & 31;
    const int g = lane >> 2, tig = lane & 3;
    const int laneM = lane & 15, laneH = lane >> 4;
    const int warpM = wid & 1, warpN = wid >> 1;

    const int ntiles = 768 / BN;
    const bool isSel = ((int)blockIdx.x >= ntiles);
    const int nbase = (isSel ? blockIdx.x - ntiles : blockIdx.x) * BN;
    const __half* __restrict__ W = isSel ? Ws : Wp;
    const float* __restrict__ bias = isSel ? bs : bp;
    float* __restrict__ out = isSel ? outG : outP;
    const int rowBase = blockIdx.y * BM;

    float c[NTL][4];
    #pragma unroll
    for (int nt = 0; nt < NTL; nt++)
        #pragma unroll
        for (int j = 0; j < 4; j++) c[nt][j] = 0.0f;

    auto issue = [&](int it) {
        const int s = it & (STAGES - 1);
        const __half* src; int ld, kc;
        if (it < 6) { src = A0; ld = ldA0; kc = it * BK; }
        else        { src = A1; ld = ldA1; kc = (it - 6) * BK; }
        #pragma unroll
        for (int i = 0; i < 2; i++) {
            int idx = tid + i * 256;
            int row = idx >> 4, ch = idx & 15;
            int gr = rowBase + row;
            uint32_t dst = sA_u + s * A_BYTES + (uint32_t)(row * LDA + ch * 8) * 2u;
            const __half* gsrc = src + (size_t)gr * ld + kc + ch * 8;
            int sz = (gr < M) ? 16 : 0;
            asm volatile("cp.async.cg.shared.global [%0], [%1], 16, %2;"
                         :: "r"(dst), "l"(gsrc), "r"(sz));
        }
        const int kb = it * BK;
        #pragma unroll
        for (int i = 0; i < 4; i++) {
            int idx = tid + i * 256;
            int krow = idx >> 3, ch = idx & 7;
            int swc = (ch ^ krow) & 7;
            uint32_t dst = sB_u + s * B_BYTES + (uint32_t)(krow * BN + swc * 8) * 2u;
            const __half* gsrc = W + (size_t)(kb + krow) * D + nbase + ch * 8;
            asm volatile("cp.async.cg.shared.global [%0], [%1], 16, 16;"
                         :: "r"(dst), "l"(gsrc));
        }
        asm volatile("cp.async.commit_group;" ::: "memory");
    };

    issue(0); issue(1); issue(2);

    for (int it = 0; it < NITER; it++) {
        if (it + STAGES - 1 < NITER) issue(it + STAGES - 1);
        else asm volatile("cp.async.commit_group;" ::: "memory");
        asm volatile("cp.async.wait_group %0;" :: "n"(STAGES - 1));
        __syncthreads();

        const int s = it & (STAGES - 1);
        const uint32_t Ab = sA_u + s * A_BYTES;
        const uint32_t Bb = sB_u + s * B_BYTES;
        #pragma unroll
        for (int ks = 0; ks < 8; ks++) {
            uint32_t a[4];
            {
                int rowA = warpM * 16 + laneM;
                uint32_t addr = Ab + (uint32_t)(rowA * LDA + laneH * 8 + ks * 16) * 2u;
                ldsm_x4(a[0], a[1], a[2], a[3], addr);
            }
            uint32_t b[NTL][2];
            {
                int krow = ks * 16 + laneM;
                int ch = warpN * 2 + laneH;
                int swc = (ch ^ krow) & 7;
                uint32_t addr = Bb + (uint32_t)(krow * BN + swc * 8) * 2u;
                uint32_t r0, r1, r2, r3;
                ldsm_x4_t(r0, r1, r2, r3, addr);
                b[0][0] = r0; b[0][1] = r1;
                b[1][0] = r2; b[1][1] = r3;
            }
            #pragma unroll
            for (int nt = 0; nt < NTL; nt++)
                asm volatile(
                    "mma.sync.aligned.m16n8k16.row.col.f32.f16.f16.f32 "
                    "{%0,%1,%2,%3}, {%4,%5,%6,%7}, {%8,%9}, {%0,%1,%2,%3};"
                    : "+f"(c[nt][0]), "+f"(c[nt][1]), "+f"(c[nt][2]), "+f"(c[nt][3])
                    : "r"(a[0]), "r"(a[1]), "r"(a[2]), "r"(a[3]),
                      "r"(b[nt][0]), "r"(b[nt][1]));
        }
        __syncthreads();
    }

    #pragma unroll
    for (int i = 0; i < 2; i++) {
        int gr = rowBase + warpM * 16 + g + i * 8;
        float ss = 0.0f;
        #pragma unroll
        for (int nt = 0; nt < NTL; nt++) {
            int col = nbase + warpN * 16 + nt * 8 + tig * 2;
            float v0 = c[nt][i * 2 + 0] + bias[col];
            float v1 = c[nt][i * 2 + 1] + bias[col + 1];
            if (isSel) {
                v0 = 1.0f / (1.0f + expf(-v0));
                v1 = 1.0f / (1.0f + expf(-v1));
            } else {
                ss += v0 * v0 + v1 * v1;
            }
            if (gr < M)
                *reinterpret_cast<float2*>(out + (size_t)gr * D + col) = make_float2(v0, v1);
        }
        if (!isSel) {
            ss += __shfl_xor_sync(0xffffffffu, ss, 1);
            ss += __shfl_xor_sync(0xffffffffu, ss, 2);
            if (tig == 0 && gr < M) atomicAdd(SSQrow + gr, ss);
        }
    }
}

// ---------------- block reduce (192 threads) ----------------
__device__ __forceinline__ float blockReduceSum192(float v) {
    __shared__ float sh[6];
    __shared__ float s_tot;
    int lane = threadIdx.x & 31;
    int wd = threadIdx.x >> 5;
    #pragma unroll
    for (int o = 16; o > 0; o >>= 1) v += __shfl_down_sync(0xffffffffu, v, o);
    if (lane == 0) sh[wd] = v;
    __syncthreads();
    if (wd == 0) {
        float t = (lane < 6) ? sh[lane] : 0.0f;
        #pragma unroll
        for (int o = 4; o > 0; o >>= 1) t += __shfl_down_sync(0xffffffffu, t, o);
        if (lane == 0) s_tot = t;
    }
    __syncthreads();
    return s_tot;
}

// ---------------- LIF (rmsnorm + inv fused): chunked 64-tap recurrence on XP ----------------
// blocks: gridDim.x = BATCH * nchunks * 3; block covers 256 consecutive d of one (b, chunk).
__global__ void lif_chunk(const float* __restrict__ xp, float* __restrict__ spk,
                          const float* __restrict__ ssq, const float* __restrict__ nw,
                          const float* __restrict__ tau_a, const float* __restrict__ th_a,
                          int Tn, int nchunks) {
    __shared__ float sInv[320];
    const int bid = blockIdx.x;
    const int dblk = bid % 3;
    const int chunk = (bid / 3) % nchunks;
    const int b = bid / (3 * nchunks);
    const int d = dblk * 256 + threadIdx.x;

    const int t0 = chunk * 256;
    int tend = t0 + 256; if (tend > Tn) tend = Tn;
    int ws = t0 - 63; if (ws < 0) ws = 0;
    const int count = tend - ws;

    const float* ssqb = ssq + (size_t)b * Tn;
    for (int j = threadIdx.x; j < count; j += 256)
        sInv[j] = rsqrtf(ssqb[ws + j] * (1.0f / (float)D) + EPSV);
    __syncthreads();

    float tau = tau_a[d], th = th_a[d], wd = nw[d];
    const float* col = xp + (size_t)b * Tn * D + d;
    float* so = spk + (size_t)b * Tn * D + d;
    float v = 0.0f;
    for (int t = ws; t < t0; t++)
        v = fmaf(tau, v, col[(size_t)t * D] * sInv[t - ws] * wd);
    for (int t = t0; t < tend; t++) {
        v = fmaf(tau, v, col[(size_t)t * D] * sInv[t - ws] * wd);
        so[(size_t)t * D] = (v >= th) ? 1.0f : 0.0f;
    }
}

// ---------------- combines (192 threads, float4, dual fp32+fp16 writes) ----------------
__global__ void combine_up(const float4* __restrict__ xp, const float4* __restrict__ gt,
                           const float4* __restrict__ spk, const float* __restrict__ cur,
                           float4* __restrict__ outS, __half2* __restrict__ outH) {
    const int r = blockIdx.x;
    const int i = threadIdx.x;
    const size_t o = (size_t)r * 192 + i;
    float4 sp = spk[o];
    float denom = blockReduceSum192(sp.x + sp.y + sp.z + sp.w);
    denom = denom > 1.0f ? denom : 1.0f;
    float id = 1.0f / denom;
    float4 xv = xp[o], gv = gt[o];
    const float4* crow = reinterpret_cast<const float4*>(cur + (size_t)r * K2);
    float4 c0 = crow[i], c1 = crow[i + 192];
    float4 ov;
    ov.x = gv.x * (xv.x + sp.x * id) + (1.0f - gv.x) * 0.5f * (c0.x + c1.x);
    ov.y = gv.y * (xv.y + sp.y * id) + (1.0f - gv.y) * 0.5f * (c0.y + c1.y);
    ov.z = gv.z * (xv.z + sp.z * id) + (1.0f - gv.z) * 0.5f * (c0.z + c1.z);
    ov.w = gv.w * (xv.w + sp.w * id) + (1.0f - gv.w) * 0.5f * (c0.w + c1.w);
    outS[o] = ov;
    outH[o * 2 + 0] = __floats2half2_rn(ov.x, ov.y);
    outH[o * 2 + 1] = __floats2half2_rn(ov.z, ov.w);
}

__global__ void combine_down(const float4* __restrict__ xp, const float4* __restrict__ gt,
                             const float4* __restrict__ spk, const float4* __restrict__ ctx,
                             float4* __restrict__ ctxN, __half2* __restrict__ ctxNh) {
    const int r = blockIdx.x;
    const int i = threadIdx.x;
    const size_t o = (size_t)r * 192 + i;
    float4 sp = spk[o];
    float denom = blockReduceSum192(sp.x + sp.y + sp.z + sp.w);
    denom = denom > 1.0f ? denom : 1.0f;
    float id = 1.0f / denom;
    float4 xv = xp[o], gv = gt[o], cv = ctx[o];
    float4 cr;
    cr.x = gv.x * (xv.x + sp.x * id) + (1.0f - gv.x) * cv.x;
    cr.y = gv.y * (xv.y + sp.y * id) + (1.0f - gv.y) * cv.y;
    cr.z = gv.z * (xv.z + sp.z * id) + (1.0f - gv.z) * cv.z;
    cr.w = gv.w * (xv.w + sp.w * id) + (1.0f - gv.w) * cv.w;
    size_t o0 = (size_t)(2 * r) * 192 + i;
    size_t o1 = (size_t)(2 * r + 1) * 192 + i;
    ctxN[o0] = cv;
    ctxN[o1] = cr;
    ctxNh[o0 * 2 + 0] = __floats2half2_rn(cv.x, cv.y);
    ctxNh[o0 * 2 + 1] = __floats2half2_rn(cv.z, cv.w);
    ctxNh[o1 * 2 + 0] = __floats2half2_rn(cr.x, cr.y);
    ctxNh[o1 * 2 + 1] = __floats2half2_rn(cr.z, cr.w);
}

__global__ void combine_leaf(const float4* __restrict__ xp, const float4* __restrict__ gt,
                             const float4* __restrict__ spk, const float4* __restrict__ x,
                             float4* __restrict__ out) {
    const int r = blockIdx.x;
    const int i = threadIdx.x;
    const size_t o = (size_t)r * 192 + i;
    float4 sp = spk[o];
    float denom = blockReduceSum192(sp.x + sp.y + sp.z + sp.w);
    denom = denom > 1.0f ? denom : 1.0f;
    float id = 1.0f / denom;
    float4 xv = xp[o], gv = gt[o], x0 = x[o];
    float4 ov;
    ov.x = gv.x * (xv.x + sp.x * id) + (1.0f - gv.x) * x0.x;
    ov.y = gv.y * (xv.y + sp.y * id) + (1.0f - gv.y) * x0.y;
    ov.z = gv.z * (xv.z + sp.z * id) + (1.0f - gv.z) * x0.z;
    ov.w = gv.w * (xv.w + sp.w * id) + (1.0f - gv.w) * x0.w;
    out[o] = ov;
}

__global__ void zero_ctx(float* __restrict__ p, __half* __restrict__ ph, int n) {
    int i = blockIdx.x * 256 + threadIdx.x;
    if (i < n) { p[i] = 0.0f; ph[i] = __float2half(0.0f); }
}

// ---------------- launcher ----------------
extern "C" void kernel_launch(void* const* d_in, const int* in_sizes, int n_in,
                              void* d_out, int out_size) {
    const float* x     = (const float*)d_in[0];
    const float* upW   = (const float*)d_in[1];
    const float* upB   = (const float*)d_in[2];
    const float* upSW  = (const float*)d_in[3];
    const float* upSB  = (const float*)d_in[4];
    const float* upNW  = (const float*)d_in[5];
    const float* upTH  = (const float*)d_in[6];
    const float* upTAU = (const float*)d_in[7];
    const float* dnW   = (const float*)d_in[8];
    const float* dnB   = (const float*)d_in[9];
    const float* dnSW  = (const float*)d_in[10];
    const float* dnSB  = (const float*)d_in[11];
    const float* dnNW  = (const float*)d_in[12];
    const float* dnTH  = (const float*)d_in[13];
    const float* dnTAU = (const float*)d_in[14];
    const float* lfSW  = (const float*)d_in[15];
    const float* lfSB  = (const float*)d_in[16];
    const float* lfW   = (const float*)d_in[17];
    const float* lfB   = (const float*)d_in[18];
    const float* lfNW  = (const float*)d_in[19];
    const float* lfTH  = (const float*)d_in[20];
    const float* lfTAU = (const float*)d_in[21];
    float* out = (float*)d_out;

    float *S, *cA, *cB, *XP, *GT, *SPK, *SSQ;
    __half *SH, *XH, *cAh, *cBh, *WH;
    cudaGetSymbolAddress((void**)&S, g_S);
    cudaGetSymbolAddress((void**)&cA, g_ctxA);
    cudaGetSymbolAddress((void**)&cB, g_ctxB);
    cudaGetSymbolAddress((void**)&XP, g_XP);
    cudaGetSymbolAddress((void**)&GT, g_GT);
    cudaGetSymbolAddress((void**)&SPK, g_SPK);
    cudaGetSymbolAddress((void**)&SSQ, g_SSQ);
    cudaGetSymbolAddress((void**)&SH, g_SH);
    cudaGetSymbolAddress((void**)&XH, g_XH);
    cudaGetSymbolAddress((void**)&cAh, g_cAh);
    cudaGetSymbolAddress((void**)&cBh, g_cBh);
    cudaGetSymbolAddress((void**)&WH, g_WH);

    const int SMEM128 = 4 * (128 * 40 * 2 + 32 * 128 * 2);   // 73728
    const int SMEMS   = 4 * (32 * 136 * 2 + 128 * 64 * 2);   // 100352
    cudaFuncSetAttribute(gemm_h<128, 2, 2>, cudaFuncAttributeMaxDynamicSharedMemorySize, SMEM128);
    cudaFuncSetAttribute(gemm_s, cudaFuncAttributeMaxDynamicSharedMemorySize, SMEMS);

    {
        size_t n4 = 46ull * KD / 4;
        convert_weights<<<(unsigned)((n4 + 255) / 256), 256>>>(upW, upSW, dnW, dnSW, lfW, lfSW,
                                                               (__half2*)WH);
        int xn4 = BATCH * TSEQ * D / 4;
        convert_x<<<(xn4 + 255) / 256, 256>>>((const float4*)x, (__half2*)XH, xn4);
        zero_ssq<<<768, 256>>>(SSQ);
    }

    int stage = 0;
    float* SSQrow = SSQ;
    auto launch_gemm = [&](const __half* A0, int ldA0, const __half* A1, int ldA1,
                           const __half* Wpp, const __half* Wss,
                           const float* bpp, const float* bss, int M) {
        SSQrow = SSQ + (size_t)stage * 8192;
        stage++;
        if (M >= 1024) {
            dim3 g(12, (M + 127) / 128);
            gemm_h<128, 2, 2><<<g, 256, SMEM128>>>(A0, ldA0, A1, ldA1, Wpp, Wss, bpp, bss,
                                                   XP, GT, SSQrow, M);
        } else {
            dim3 g(24, (M + 31) / 32);
            gemm_s<<<g, 256, SMEMS>>>(A0, ldA0, A1, ldA1, Wpp, Wss, bpp, bss,
                                      XP, GT, SSQrow, M);
        }
    };

    size_t soff[NLEV + 1];
    soff[1] = 0;
    for (int k = 1; k < NLEV; k++)
        soff[k + 1] = soff[k] + (size_t)BATCH * (TSEQ >> k) * D;

    // ---- up pass ----
    const float* cur = x;
    const __half* curH = XH;
    int Tl = TSEQ;
    for (int l = 0; l < NLEV; l++) {
        int Tn = Tl >> 1;
        int M = BATCH * Tn;
        float* Sout = S + soff[l + 1];
        __half* SoutH = SH + soff[l + 1];
        launch_gemm(curH, K2, curH + D, K2,
                    WH + (size_t)l * KD, WH + (size_t)(11 + l) * KD,
                    upB + (size_t)l * D, upSB + (size_t)l * D, M);
        int nch = (Tn + 255) / 256;
        lif_chunk<<<BATCH * nch * 3, 256>>>(XP, SPK, SSQrow, upNW + (size_t)l * D,
                                            upTAU + (size_t)l * D, upTH + (size_t)l * D, Tn, nch);
        combine_up<<<M, 192>>>((const float4*)XP, (const float4*)GT, (const float4*)SPK,
                               cur, (float4*)Sout, (__half2*)SoutH);
        cur = Sout;
        curH = SoutH;
        Tl = Tn;
    }

    // ---- down pass ----
    zero_ctx<<<(BATCH * D + 255) / 256, 256>>>(cA, cAh, BATCH * D);
    float* ctx = cA;  __half* ctxh = cAh;
    float* ctxN = cB; __half* ctxNh = cBh;
    int n = 1;
    for (int l = NLEV; l >= 1; l--) {
        int i = l - 1;
        int M = BATCH * n;
        const __half* childH = (i == 0) ? XH : (SH + soff[i]);
        launch_gemm(ctxh, D, childH, 2 * D,
                    WH + (size_t)(22 + i) * KD, WH + (size_t)(33 + i) * KD,
                    dnB + (size_t)i * D, dnSB + (size_t)i * D, M);
        int nch = (n + 255) / 256;
        lif_chunk<<<BATCH * nch * 3, 256>>>(XP, SPK, SSQrow, dnNW + (size_t)i * D,
                                            dnTAU + (size_t)i * D, dnTH + (size_t)i * D, n, nch);
        combine_down<<<M, 192>>>((const float4*)XP, (const float4*)GT, (const float4*)SPK,
                                 (const float4*)ctx, (float4*)ctxN, (__half2*)ctxNh);
        float* t1 = ctx; ctx = ctxN; ctxN = t1;
        __half* t2 = ctxh; ctxh = ctxNh; ctxNh = t2;
        n <<= 1;
    }

    // ---- leaf fusion ----
    {
        int M = BATCH * TSEQ;
        launch_gemm(XH, D, ctxh, D,
                    WH + 44ull * KD, WH + 45ull * KD, lfB, lfSB, M);
        int nch = (TSEQ + 255) / 256;
        lif_chunk<<<BATCH * nch * 3, 256>>>(XP, SPK, SSQrow, lfNW, lfTAU, lfTH, TSEQ, nch);
        combine_leaf<<<M, 192>>>((const float4*)XP, (const float4*)GT, (const float4*)SPK,
                                 (const float4*)x, (float4*)out);
    }
}